// round 1
// baseline (speedup 1.0000x reference)
#include <cuda_runtime.h>
#include <cuda_bf16.h>
#include <math.h>

// ---------------------------------------------------------------------------
// Problem constants
// ---------------------------------------------------------------------------
#define S_LEN 2048
#define D_MODEL 4096
#define N_HEADS 32
#define N_KV_HEADS 8
#define HEAD_DIM 128
#define QK_SCALE 0.08838834764831845f  // 1/sqrt(128)

// ---------------------------------------------------------------------------
// Scratch (device globals; no allocation allowed)
// ---------------------------------------------------------------------------
__device__ float g_q[S_LEN * N_HEADS * HEAD_DIM];      // 2048 x 4096
__device__ float g_k[S_LEN * N_KV_HEADS * HEAD_DIM];   // 2048 x 1024
__device__ float g_v[S_LEN * N_KV_HEADS * HEAD_DIM];   // 2048 x 1024
__device__ float g_att[S_LEN * N_HEADS * HEAD_DIM];    // 2048 x 4096

// ---------------------------------------------------------------------------
// SGEMM: C[M,N] = A[M,K] @ B[K,N], all row-major, M%128==0, N%128==0, K%16==0
// 128x128 tile, BK=16, 256 threads, 8x8 per-thread microtile.
// ---------------------------------------------------------------------------
#define GBM 128
#define GBN 128
#define GBK 16

__global__ __launch_bounds__(256) void sgemm_kernel(
    const float* __restrict__ A, const float* __restrict__ B,
    float* __restrict__ C, int M, int N, int K)
{
    __shared__ float As[GBK][GBM];   // transposed A tile
    __shared__ float Bs[GBK][GBN];

    const int bx = blockIdx.x;  // N tile
    const int by = blockIdx.y;  // M tile
    const int tid = threadIdx.x;
    const int tx = tid & 15;
    const int ty = tid >> 4;

    const float* Ab = A + (size_t)by * GBM * K;
    const float* Bb = B + (size_t)bx * GBN;

    float acc[8][8];
#pragma unroll
    for (int i = 0; i < 8; i++)
#pragma unroll
        for (int j = 0; j < 8; j++) acc[i][j] = 0.f;

    const int arow = tid >> 2;            // 0..63 (also +64)
    const int acol4 = (tid & 3) << 2;     // 0,4,8,12
    const int brow = tid >> 5;            // 0..7 (also +8)
    const int bcol4 = (tid & 31) << 2;    // 0..124

    for (int k0 = 0; k0 < K; k0 += GBK) {
#pragma unroll
        for (int r = 0; r < 2; r++) {
            int row = arow + r * 64;
            float4 v = *(const float4*)(Ab + (size_t)row * K + k0 + acol4);
            As[acol4 + 0][row] = v.x;
            As[acol4 + 1][row] = v.y;
            As[acol4 + 2][row] = v.z;
            As[acol4 + 3][row] = v.w;
        }
#pragma unroll
        for (int r = 0; r < 2; r++) {
            int row = brow + r * 8;
            *(float4*)(&Bs[row][bcol4]) =
                *(const float4*)(Bb + (size_t)(k0 + row) * N + bcol4);
        }
        __syncthreads();

#pragma unroll
        for (int kk = 0; kk < GBK; kk++) {
            float af[8], bf[8];
#pragma unroll
            for (int i = 0; i < 8; i++) af[i] = As[kk][ty * 8 + i];
#pragma unroll
            for (int j = 0; j < 8; j++) bf[j] = Bs[kk][tx * 8 + j];
#pragma unroll
            for (int i = 0; i < 8; i++)
#pragma unroll
                for (int j = 0; j < 8; j++)
                    acc[i][j] = fmaf(af[i], bf[j], acc[i][j]);
        }
        __syncthreads();
    }

    float* Cb = C + (size_t)by * GBM * N + (size_t)bx * GBN;
#pragma unroll
    for (int i = 0; i < 8; i++) {
#pragma unroll
        for (int j = 0; j < 8; j += 4) {
            float4 v = make_float4(acc[i][j], acc[i][j + 1], acc[i][j + 2], acc[i][j + 3]);
            *(float4*)(&Cb[(size_t)(ty * 8 + i) * N + tx * 8 + j]) = v;
        }
    }
}

// ---------------------------------------------------------------------------
// RoPE (interleaved pairs): t[..., 2i], t[..., 2i+1] rotated by (cos,sin)[s,i]
// tensor layout: [S, Hn, 128]
// ---------------------------------------------------------------------------
__global__ void rope_kernel(float* __restrict__ t,
                            const float* __restrict__ cosp,
                            const float* __restrict__ sinp,
                            int total, int Hn)
{
    int idx = blockIdx.x * blockDim.x + threadIdx.x;
    if (idx >= total) return;
    int p = idx & 63;
    int h = (idx >> 6) % Hn;
    int s = idx / (64 * Hn);
    float c = cosp[s * 64 + p];
    float sn = sinp[s * 64 + p];
    float* base = t + ((size_t)s * Hn + h) * HEAD_DIM;
    float t0 = base[2 * p];
    float t1 = base[2 * p + 1];
    base[2 * p]     = t0 * c - t1 * sn;
    base[2 * p + 1] = t0 * sn + t1 * c;
}

// ---------------------------------------------------------------------------
// Flash attention (causal, GQA 4:1), fp32, BM=BN=64, 256 threads.
// Q: [S, 32, 128], K/V: [S, 8, 128], O: [S, 32, 128]
// Smem: Qs[64][129], Kt[128][65] (transposed), Vs[64][128], Ps[64][65]
// ---------------------------------------------------------------------------
#define ATT_SMEM_FLOATS (64*129 + 128*65 + 64*128 + 64*65 + 64 + 64)
#define ATT_SMEM_BYTES (ATT_SMEM_FLOATS * 4)

__global__ __launch_bounds__(256) void attn_kernel(
    const float* __restrict__ Q, const float* __restrict__ K,
    const float* __restrict__ V, float* __restrict__ O)
{
    extern __shared__ float sm[];
    float* Qs = sm;                      // [64][129]
    float* Kt = Qs + 64 * 129;           // [128][65]
    float* Vs = Kt + 128 * 65;           // [64][128]
    float* Ps = Vs + 64 * 128;           // [64][65]
    float* rowscale = Ps + 64 * 65;      // [64]
    float* rowl = rowscale + 64;         // [64]

    const int qblk = blockIdx.x;         // 0..31
    const int h = blockIdx.y;            // 0..31
    const int kvh = h >> 2;              // GQA: 4 q-heads per kv-head
    const int tid = threadIdx.x;
    const int tx = tid & 15, ty = tid >> 4;
    const int warp = tid >> 5, lane = tid & 31;
    const int q0 = qblk * 64;

    // Load Q tile (pre-scaled by 1/sqrt(HD))
    for (int idx = tid; idx < 64 * 32; idx += 256) {
        int r = idx >> 5;
        int c4 = (idx & 31) << 2;
        float4 v = *(const float4*)(Q + (size_t)(q0 + r) * 4096 + h * 128 + c4);
        Qs[r * 129 + c4 + 0] = v.x * QK_SCALE;
        Qs[r * 129 + c4 + 1] = v.y * QK_SCALE;
        Qs[r * 129 + c4 + 2] = v.z * QK_SCALE;
        Qs[r * 129 + c4 + 3] = v.w * QK_SCALE;
    }

    float o[8][4];
#pragma unroll
    for (int i = 0; i < 8; i++)
#pragma unroll
        for (int j = 0; j < 4; j++) o[i][j] = 0.f;
    float m_i[4], l_i[4];
#pragma unroll
    for (int i = 0; i < 4; i++) { m_i[i] = -1e30f; l_i[i] = 0.f; }

    const int ntiles = qblk + 1;
    for (int t = 0; t < ntiles; t++) {
        // Load K tile transposed + V tile
        for (int idx = tid; idx < 64 * 32; idx += 256) {
            int r = idx >> 5;
            int c4 = (idx & 31) << 2;
            float4 kv = *(const float4*)(K + (size_t)(t * 64 + r) * 1024 + kvh * 128 + c4);
            Kt[(c4 + 0) * 65 + r] = kv.x;
            Kt[(c4 + 1) * 65 + r] = kv.y;
            Kt[(c4 + 2) * 65 + r] = kv.z;
            Kt[(c4 + 3) * 65 + r] = kv.w;
            *(float4*)(Vs + r * 128 + c4) =
                *(const float4*)(V + (size_t)(t * 64 + r) * 1024 + kvh * 128 + c4);
        }
        __syncthreads();

        // S = Qs @ Kt  (thread: rows ty*4+i, cols tx+16*j)
        float s[4][4];
#pragma unroll
        for (int i = 0; i < 4; i++)
#pragma unroll
            for (int j = 0; j < 4; j++) s[i][j] = 0.f;

#pragma unroll 4
        for (int d = 0; d < 128; d++) {
            float a[4], b[4];
#pragma unroll
            for (int i = 0; i < 4; i++) a[i] = Qs[(ty * 4 + i) * 129 + d];
#pragma unroll
            for (int j = 0; j < 4; j++) b[j] = Kt[d * 65 + tx + 16 * j];
#pragma unroll
            for (int i = 0; i < 4; i++)
#pragma unroll
                for (int j = 0; j < 4; j++)
                    s[i][j] = fmaf(a[i], b[j], s[i][j]);
        }

        // Causal mask on diagonal tile (local coords; blocks are aligned)
        if (t == qblk) {
#pragma unroll
            for (int i = 0; i < 4; i++)
#pragma unroll
                for (int j = 0; j < 4; j++)
                    if (tx + 16 * j > ty * 4 + i) s[i][j] = -1e30f;
        }

        // Online softmax (reduce across the 16 tx-lanes of each row)
#pragma unroll
        for (int i = 0; i < 4; i++) {
            float mx = fmaxf(fmaxf(s[i][0], s[i][1]), fmaxf(s[i][2], s[i][3]));
#pragma unroll
            for (int off = 1; off < 16; off <<= 1)
                mx = fmaxf(mx, __shfl_xor_sync(0xffffffffu, mx, off));
            float mnew = fmaxf(m_i[i], mx);
            float sum = 0.f;
#pragma unroll
            for (int j = 0; j < 4; j++) {
                float p = __expf(s[i][j] - mnew);
                s[i][j] = p;
                sum += p;
            }
#pragma unroll
            for (int off = 1; off < 16; off <<= 1)
                sum += __shfl_xor_sync(0xffffffffu, sum, off);
            float sc = __expf(m_i[i] - mnew);
            l_i[i] = l_i[i] * sc + sum;
            m_i[i] = mnew;
            if (tx == 0) rowscale[ty * 4 + i] = sc;
#pragma unroll
            for (int j = 0; j < 4; j++)
                Ps[(ty * 4 + i) * 65 + tx + 16 * j] = s[i][j];
        }
        __syncthreads();

        // O = O*scale + Ps @ Vs  (warp owns rows warp*8..+7, lane owns 4 cols)
#pragma unroll
        for (int i = 0; i < 8; i++) {
            float sc = rowscale[warp * 8 + i];
#pragma unroll
            for (int j = 0; j < 4; j++) o[i][j] *= sc;
        }
#pragma unroll 4
        for (int kk = 0; kk < 64; kk++) {
            float4 v4 = *(float4*)(Vs + kk * 128 + lane * 4);
#pragma unroll
            for (int i = 0; i < 8; i++) {
                float p = Ps[(warp * 8 + i) * 65 + kk];
                o[i][0] = fmaf(p, v4.x, o[i][0]);
                o[i][1] = fmaf(p, v4.y, o[i][1]);
                o[i][2] = fmaf(p, v4.z, o[i][2]);
                o[i][3] = fmaf(p, v4.w, o[i][3]);
            }
        }
        __syncthreads();
    }

    if (tx == 0) {
#pragma unroll
        for (int i = 0; i < 4; i++) rowl[ty * 4 + i] = l_i[i];
    }
    __syncthreads();

#pragma unroll
    for (int i = 0; i < 8; i++) {
        int row = warp * 8 + i;
        float inv = 1.f / rowl[row];
        float4 r4 = make_float4(o[i][0] * inv, o[i][1] * inv,
                                o[i][2] * inv, o[i][3] * inv);
        *(float4*)(O + (size_t)(q0 + row) * 4096 + h * 128 + lane * 4) = r4;
    }
}

// ---------------------------------------------------------------------------
// Launch
// inputs: 0:x 1:wq 2:wk 3:wv 4:wo 5:freqs_cos 6:freqs_sin 7:mask 8:start_pos 9:init_seqlen
// ---------------------------------------------------------------------------
extern "C" void kernel_launch(void* const* d_in, const int* in_sizes, int n_in,
                              void* d_out, int out_size)
{
    const float* x    = (const float*)d_in[0];
    const float* wq   = (const float*)d_in[1];
    const float* wk   = (const float*)d_in[2];
    const float* wv   = (const float*)d_in[3];
    const float* wo   = (const float*)d_in[4];
    const float* cosp = (const float*)d_in[5];
    const float* sinp = (const float*)d_in[6];

    float *q, *k, *v, *att;
    cudaGetSymbolAddress((void**)&q, g_q);
    cudaGetSymbolAddress((void**)&k, g_k);
    cudaGetSymbolAddress((void**)&v, g_v);
    cudaGetSymbolAddress((void**)&att, g_att);

    // QKV projections
    sgemm_kernel<<<dim3(D_MODEL / GBN, S_LEN / GBM), 256>>>(x, wq, q, S_LEN, D_MODEL, D_MODEL);
    sgemm_kernel<<<dim3((N_KV_HEADS * HEAD_DIM) / GBN, S_LEN / GBM), 256>>>(x, wk, k, S_LEN, N_KV_HEADS * HEAD_DIM, D_MODEL);
    sgemm_kernel<<<dim3((N_KV_HEADS * HEAD_DIM) / GBN, S_LEN / GBM), 256>>>(x, wv, v, S_LEN, N_KV_HEADS * HEAD_DIM, D_MODEL);

    // RoPE on Q and K
    {
        int totq = S_LEN * N_HEADS * 64;
        rope_kernel<<<(totq + 255) / 256, 256>>>(q, cosp, sinp, totq, N_HEADS);
        int totk = S_LEN * N_KV_HEADS * 64;
        rope_kernel<<<(totk + 255) / 256, 256>>>(k, cosp, sinp, totk, N_KV_HEADS);
    }

    // Flash attention
    cudaFuncSetAttribute(attn_kernel, cudaFuncAttributeMaxDynamicSharedMemorySize, ATT_SMEM_BYTES);
    attn_kernel<<<dim3(S_LEN / 64, N_HEADS), 256, ATT_SMEM_BYTES>>>(q, k, v, att);

    // Output projection
    sgemm_kernel<<<dim3(D_MODEL / GBN, S_LEN / GBM), 256>>>(att, wo, (float*)d_out, S_LEN, D_MODEL, D_MODEL);
}

// round 3
// speedup vs baseline: 1.7534x; 1.7534x over previous
#include <cuda_runtime.h>
#include <cuda_bf16.h>
#include <math.h>
#include <stdint.h>

// ---------------------------------------------------------------------------
// Problem constants
// ---------------------------------------------------------------------------
#define S_LEN 2048
#define D_MODEL 4096
#define N_HEADS 32
#define N_KV_HEADS 8
#define HEAD_DIM 128
#define QKV_N 6144                       // 4096 + 1024 + 1024
#define QK_SCALE 0.08838834764831845f    // 1/sqrt(128)

// ---------------------------------------------------------------------------
// Scratch (device globals; allocation is forbidden)
// ---------------------------------------------------------------------------
__device__ unsigned short g_xhi[S_LEN * D_MODEL];
__device__ unsigned short g_xlo[S_LEN * D_MODEL];
__device__ unsigned short g_wqkvT_hi[QKV_N * D_MODEL];
__device__ unsigned short g_wqkvT_lo[QKV_N * D_MODEL];
__device__ unsigned short g_woT_hi[D_MODEL * D_MODEL];
__device__ unsigned short g_woT_lo[D_MODEL * D_MODEL];
__device__ float g_qkv[S_LEN * QKV_N];
__device__ float g_att[S_LEN * D_MODEL];
__device__ unsigned short g_atthi[S_LEN * D_MODEL];
__device__ unsigned short g_attlo[S_LEN * D_MODEL];

// ---------------------------------------------------------------------------
// Baseline-PTX helpers (NO tcgen05/TMA — harness compiles for compute_103)
// ---------------------------------------------------------------------------
__device__ __forceinline__ uint32_t cvta_shared(const void* p) {
    return (uint32_t)__cvta_generic_to_shared(p);
}
__device__ __forceinline__ void cp16(uint32_t dst, const void* src) {
    asm volatile("cp.async.cg.shared.global [%0], [%1], 16;" :: "r"(dst), "l"(src) : "memory");
}
__device__ __forceinline__ void cp_commit() {
    asm volatile("cp.async.commit_group;" ::: "memory");
}
template <int N> __device__ __forceinline__ void cp_wait() {
    asm volatile("cp.async.wait_group %0;" :: "n"(N) : "memory");
}
__device__ __forceinline__ void ldsm4(uint32_t* r, uint32_t addr) {
    asm volatile("ldmatrix.sync.aligned.m8n8.x4.shared.b16 {%0,%1,%2,%3}, [%4];"
                 : "=r"(r[0]), "=r"(r[1]), "=r"(r[2]), "=r"(r[3]) : "r"(addr));
}
__device__ __forceinline__ void mma_bf16(float* c, const uint32_t* a, const uint32_t* b) {
    asm volatile(
        "mma.sync.aligned.m16n8k16.row.col.f32.bf16.bf16.f32 "
        "{%0,%1,%2,%3}, {%4,%5,%6,%7}, {%8,%9}, {%0,%1,%2,%3};"
        : "+f"(c[0]), "+f"(c[1]), "+f"(c[2]), "+f"(c[3])
        : "r"(a[0]), "r"(a[1]), "r"(a[2]), "r"(a[3]), "r"(b[0]), "r"(b[1]));
}

// ---------------------------------------------------------------------------
// fp32 -> bf16 hi/lo split (elementwise, vectorized)
// ---------------------------------------------------------------------------
__global__ void split_kernel(const float* __restrict__ x,
                             unsigned short* __restrict__ hi,
                             unsigned short* __restrict__ lo, int n4) {
    int i = blockIdx.x * blockDim.x + threadIdx.x;
    if (i >= n4) return;
    float4 v = ((const float4*)x)[i];
    __nv_bfloat16 h0 = __float2bfloat16(v.x);
    __nv_bfloat16 h1 = __float2bfloat16(v.y);
    __nv_bfloat16 h2 = __float2bfloat16(v.z);
    __nv_bfloat16 h3 = __float2bfloat16(v.w);
    ushort4 hh;
    hh.x = __bfloat16_as_ushort(h0); hh.y = __bfloat16_as_ushort(h1);
    hh.z = __bfloat16_as_ushort(h2); hh.w = __bfloat16_as_ushort(h3);
    ushort4 ll;
    ll.x = __bfloat16_as_ushort(__float2bfloat16(v.x - __bfloat162float(h0)));
    ll.y = __bfloat16_as_ushort(__float2bfloat16(v.y - __bfloat162float(h1)));
    ll.z = __bfloat16_as_ushort(__float2bfloat16(v.z - __bfloat162float(h2)));
    ll.w = __bfloat16_as_ushort(__float2bfloat16(v.w - __bfloat162float(h3)));
    ((ushort4*)hi)[i] = hh;
    ((ushort4*)lo)[i] = ll;
}

// ---------------------------------------------------------------------------
// W[K x N] fp32 -> T[N x K] bf16 hi/lo (tiled transpose + split)
// ---------------------------------------------------------------------------
__global__ void split_transpose_kernel(const float* __restrict__ W,
                                       unsigned short* __restrict__ Thi,
                                       unsigned short* __restrict__ Tlo,
                                       int K, int N) {
    __shared__ float t[32][33];
    int n0 = blockIdx.x * 32, k0 = blockIdx.y * 32;
    int tx = threadIdx.x, ty = threadIdx.y;  // 32 x 8
#pragma unroll
    for (int r = 0; r < 32; r += 8)
        t[ty + r][tx] = W[(size_t)(k0 + ty + r) * N + n0 + tx];
    __syncthreads();
#pragma unroll
    for (int r = 0; r < 32; r += 8) {
        float v = t[tx][ty + r];
        __nv_bfloat16 h = __float2bfloat16(v);
        float lv = v - __bfloat162float(h);
        size_t o = (size_t)(n0 + ty + r) * K + k0 + tx;
        Thi[o] = __bfloat16_as_ushort(h);
        Tlo[o] = __bfloat16_as_ushort(__float2bfloat16(lv));
    }
}

// ---------------------------------------------------------------------------
// Warp-MMA split-bf16 GEMM: C[M,N] = (Ahi+Alo)[M,K] @ (BThi+BTlo)[N,K]^T
// CTA tile 128x128, BK=32, 8 warps (warp tile 32x64), 3-stage cp.async.
// smem rows padded to 40 halfs (80B = 5x16B, gcd(5,8)=1 -> ldmatrix
// conflict-free).
// ---------------------------------------------------------------------------
#define GT_BM 128
#define GT_BN 128
#define GT_BK 32
#define GT_ROWB 80           // bytes per smem row (40 halfs)
#define GT_TILE 10240        // 128 rows * 80B
#define GT_STAGE 40960       // Ahi,Alo,Bhi,Blo
#define GT_STAGES 3
#define GT_SMEM (GT_STAGES * GT_STAGE)

__global__ __launch_bounds__(256) void gemm_mma_kernel(
    const unsigned short* __restrict__ Ahi_, const unsigned short* __restrict__ Alo_,
    const unsigned short* __restrict__ Bhi_, const unsigned short* __restrict__ Blo_,
    float* __restrict__ C, int M, int N, int K)
{
    extern __shared__ char smem[];
    uint32_t sb = cvta_shared(smem);
    const int tid = threadIdx.x;
    const int lane = tid & 31, wid = tid >> 5;
    const int warp_m = wid & 3;   // 4 warps over M (4*32=128)
    const int warp_n = wid >> 2;  // 2 warps over N (2*64=128)
    const int m0 = blockIdx.x * GT_BM;
    const int n0 = blockIdx.y * GT_BN;

    const unsigned short* srcs[4] = {
        Ahi_ + (size_t)m0 * K, Alo_ + (size_t)m0 * K,
        Bhi_ + (size_t)n0 * K, Blo_ + (size_t)n0 * K };

    auto load_stage = [&](int ch, int st) {
        uint32_t base = sb + st * GT_STAGE;
        int k0 = ch * GT_BK;
#pragma unroll
        for (int v = 0; v < 4; v++) {
            uint32_t tb = base + v * GT_TILE;
            const unsigned short* src = srcs[v];
            for (int i = tid; i < 512; i += 256) {
                int row = i >> 2, c = i & 3;
                cp16(tb + row * GT_ROWB + c * 16,
                     src + (size_t)row * K + k0 + c * 8);
            }
        }
        cp_commit();
    };

    float acc[2][8][4];
#pragma unroll
    for (int mt = 0; mt < 2; mt++)
#pragma unroll
        for (int nt = 0; nt < 8; nt++)
#pragma unroll
            for (int r = 0; r < 4; r++) acc[mt][nt][r] = 0.f;

    const int NC = K / GT_BK;
    load_stage(0, 0);
    load_stage(1, 1);

    // lane addressing offsets (within a tile base)
    const uint32_t a_off = (uint32_t)((lane & 15) * GT_ROWB + (lane >> 4) * 16);
    const uint32_t b_off = a_off;

    for (int ch = 0; ch < NC; ch++) {
        int st = ch % GT_STAGES;
        if (ch + 2 < NC) { load_stage(ch + 2, (ch + 2) % GT_STAGES); cp_wait<2>(); }
        else if (ch + 1 < NC) { cp_wait<1>(); }
        else { cp_wait<0>(); }
        __syncthreads();

        uint32_t base = sb + st * GT_STAGE;
        uint32_t aHi = base + (warp_m * 32) * GT_ROWB + a_off;
        uint32_t aLo = aHi + GT_TILE;
        uint32_t bHi = base + 2 * GT_TILE + (warp_n * 64) * GT_ROWB + b_off;
        uint32_t bLo = bHi + GT_TILE;

#pragma unroll
        for (int k16 = 0; k16 < 2; k16++) {
            uint32_t koff = k16 * 32;  // 16 halfs = 32B
            uint32_t ahi[2][4], alo[2][4];
#pragma unroll
            for (int mt = 0; mt < 2; mt++) {
                ldsm4(ahi[mt], aHi + mt * 16 * GT_ROWB + koff);
                ldsm4(alo[mt], aLo + mt * 16 * GT_ROWB + koff);
            }
            uint32_t bh[8][2], bl[8][2];
#pragma unroll
            for (int ng = 0; ng < 4; ng++) {
                uint32_t r[4];
                ldsm4(r, bHi + ng * 16 * GT_ROWB + koff);
                bh[2 * ng][0] = r[0]; bh[2 * ng][1] = r[2];
                bh[2 * ng + 1][0] = r[1]; bh[2 * ng + 1][1] = r[3];
                ldsm4(r, bLo + ng * 16 * GT_ROWB + koff);
                bl[2 * ng][0] = r[0]; bl[2 * ng][1] = r[2];
                bl[2 * ng + 1][0] = r[1]; bl[2 * ng + 1][1] = r[3];
            }
#pragma unroll
            for (int mt = 0; mt < 2; mt++)
#pragma unroll
                for (int nt = 0; nt < 8; nt++) {
                    mma_bf16(acc[mt][nt], ahi[mt], bh[nt]);
                    mma_bf16(acc[mt][nt], alo[mt], bh[nt]);
                    mma_bf16(acc[mt][nt], ahi[mt], bl[nt]);
                }
        }
        __syncthreads();
    }

    // Epilogue: direct fp32 stores (float2 per fragment row)
#pragma unroll
    for (int mt = 0; mt < 2; mt++) {
        int row = m0 + warp_m * 32 + mt * 16 + (lane >> 2);
#pragma unroll
        for (int nt = 0; nt < 8; nt++) {
            int col = n0 + warp_n * 64 + nt * 8 + (lane & 3) * 2;
            *(float2*)&C[(size_t)row * N + col] =
                make_float2(acc[mt][nt][0], acc[mt][nt][1]);
            *(float2*)&C[(size_t)(row + 8) * N + col] =
                make_float2(acc[mt][nt][2], acc[mt][nt][3]);
        }
    }
}

// ---------------------------------------------------------------------------
// RoPE (interleaved pairs), generic row stride
// ---------------------------------------------------------------------------
__global__ void rope_kernel(float* __restrict__ t,
                            const float* __restrict__ cosp,
                            const float* __restrict__ sinp,
                            int total, int Hn, int rowStride)
{
    int idx = blockIdx.x * blockDim.x + threadIdx.x;
    if (idx >= total) return;
    int p = idx & 63;
    int h = (idx >> 6) % Hn;
    int s = idx / (64 * Hn);
    float c = cosp[s * 64 + p];
    float sn = sinp[s * 64 + p];
    float* base = t + (size_t)s * rowStride + h * HEAD_DIM;
    float t0 = base[2 * p];
    float t1 = base[2 * p + 1];
    base[2 * p]     = t0 * c - t1 * sn;
    base[2 * p + 1] = t0 * sn + t1 * c;
}

// ---------------------------------------------------------------------------
// Flash attention (causal, GQA 4:1), fp32 SIMT, BM=BN=64, 256 threads.
// qkv: [S, 6144] (Q at col 0, K at 4096, V at 5120); O: [S, 4096]
// ---------------------------------------------------------------------------
#define ATT_SMEM_FLOATS (64*129 + 128*65 + 64*128 + 64*65 + 64 + 64)
#define ATT_SMEM_BYTES (ATT_SMEM_FLOATS * 4)

__global__ __launch_bounds__(256) void attn_kernel(
    const float* __restrict__ qkv, float* __restrict__ O)
{
    extern __shared__ float sm[];
    float* Qs = sm;                      // [64][129]
    float* Kt = Qs + 64 * 129;           // [128][65]
    float* Vs = Kt + 128 * 65;           // [64][128]
    float* Ps = Vs + 64 * 128;           // [64][65]
    float* rowscale = Ps + 64 * 65;      // [64]
    float* rowl = rowscale + 64;         // [64]

    const int qblk = blockIdx.x;
    const int h = blockIdx.y;
    const int kvh = h >> 2;
    const int tid = threadIdx.x;
    const int tx = tid & 15, ty = tid >> 4;
    const int warp = tid >> 5, lane = tid & 31;
    const int q0 = qblk * 64;

    for (int idx = tid; idx < 64 * 32; idx += 256) {
        int r = idx >> 5;
        int c4 = (idx & 31) << 2;
        float4 v = *(const float4*)(qkv + (size_t)(q0 + r) * QKV_N + h * 128 + c4);
        Qs[r * 129 + c4 + 0] = v.x * QK_SCALE;
        Qs[r * 129 + c4 + 1] = v.y * QK_SCALE;
        Qs[r * 129 + c4 + 2] = v.z * QK_SCALE;
        Qs[r * 129 + c4 + 3] = v.w * QK_SCALE;
    }

    float o[8][4];
#pragma unroll
    for (int i = 0; i < 8; i++)
#pragma unroll
        for (int j = 0; j < 4; j++) o[i][j] = 0.f;
    float m_i[4], l_i[4];
#pragma unroll
    for (int i = 0; i < 4; i++) { m_i[i] = -1e30f; l_i[i] = 0.f; }

    const int ntiles = qblk + 1;
    for (int t = 0; t < ntiles; t++) {
        for (int idx = tid; idx < 64 * 32; idx += 256) {
            int r = idx >> 5;
            int c4 = (idx & 31) << 2;
            float4 kv = *(const float4*)(qkv + (size_t)(t * 64 + r) * QKV_N + 4096 + kvh * 128 + c4);
            Kt[(c4 + 0) * 65 + r] = kv.x;
            Kt[(c4 + 1) * 65 + r] = kv.y;
            Kt[(c4 + 2) * 65 + r] = kv.z;
            Kt[(c4 + 3) * 65 + r] = kv.w;
            *(float4*)(Vs + r * 128 + c4) =
                *(const float4*)(qkv + (size_t)(t * 64 + r) * QKV_N + 5120 + kvh * 128 + c4);
        }
        __syncthreads();

        float s[4][4];
#pragma unroll
        for (int i = 0; i < 4; i++)
#pragma unroll
            for (int j = 0; j < 4; j++) s[i][j] = 0.f;

#pragma unroll 4
        for (int d = 0; d < 128; d++) {
            float a[4], b[4];
#pragma unroll
            for (int i = 0; i < 4; i++) a[i] = Qs[(ty * 4 + i) * 129 + d];
#pragma unroll
            for (int j = 0; j < 4; j++) b[j] = Kt[d * 65 + tx + 16 * j];
#pragma unroll
            for (int i = 0; i < 4; i++)
#pragma unroll
                for (int j = 0; j < 4; j++)
                    s[i][j] = fmaf(a[i], b[j], s[i][j]);
        }

        if (t == qblk) {
#pragma unroll
            for (int i = 0; i < 4; i++)
#pragma unroll
                for (int j = 0; j < 4; j++)
                    if (tx + 16 * j > ty * 4 + i) s[i][j] = -1e30f;
        }

#pragma unroll
        for (int i = 0; i < 4; i++) {
            float mx = fmaxf(fmaxf(s[i][0], s[i][1]), fmaxf(s[i][2], s[i][3]));
#pragma unroll
            for (int off = 1; off < 16; off <<= 1)
                mx = fmaxf(mx, __shfl_xor_sync(0xffffffffu, mx, off));
            float mnew = fmaxf(m_i[i], mx);
            float sum = 0.f;
#pragma unroll
            for (int j = 0; j < 4; j++) {
                float p = __expf(s[i][j] - mnew);
                s[i][j] = p;
                sum += p;
            }
#pragma unroll
            for (int off = 1; off < 16; off <<= 1)
                sum += __shfl_xor_sync(0xffffffffu, sum, off);
            float sc = __expf(m_i[i] - mnew);
            l_i[i] = l_i[i] * sc + sum;
            m_i[i] = mnew;
            if (tx == 0) rowscale[ty * 4 + i] = sc;
#pragma unroll
            for (int j = 0; j < 4; j++)
                Ps[(ty * 4 + i) * 65 + tx + 16 * j] = s[i][j];
        }
        __syncthreads();

#pragma unroll
        for (int i = 0; i < 8; i++) {
            float sc = rowscale[warp * 8 + i];
#pragma unroll
            for (int j = 0; j < 4; j++) o[i][j] *= sc;
        }
#pragma unroll 4
        for (int kk = 0; kk < 64; kk++) {
            float4 v4 = *(float4*)(Vs + kk * 128 + lane * 4);
#pragma unroll
            for (int i = 0; i < 8; i++) {
                float p = Ps[(warp * 8 + i) * 65 + kk];
                o[i][0] = fmaf(p, v4.x, o[i][0]);
                o[i][1] = fmaf(p, v4.y, o[i][1]);
                o[i][2] = fmaf(p, v4.z, o[i][2]);
                o[i][3] = fmaf(p, v4.w, o[i][3]);
            }
        }
        __syncthreads();
    }

    if (tx == 0) {
#pragma unroll
        for (int i = 0; i < 4; i++) rowl[ty * 4 + i] = l_i[i];
    }
    __syncthreads();

#pragma unroll
    for (int i = 0; i < 8; i++) {
        int row = warp * 8 + i;
        float inv = 1.f / rowl[row];
        float4 r4 = make_float4(o[i][0] * inv, o[i][1] * inv,
                                o[i][2] * inv, o[i][3] * inv);
        *(float4*)(O + (size_t)(q0 + row) * 4096 + h * 128 + lane * 4) = r4;
    }
}

// ---------------------------------------------------------------------------
// Launch
// inputs: 0:x 1:wq 2:wk 3:wv 4:wo 5:freqs_cos 6:freqs_sin 7:mask 8:start_pos 9:init_seqlen
// ---------------------------------------------------------------------------
extern "C" void kernel_launch(void* const* d_in, const int* in_sizes, int n_in,
                              void* d_out, int out_size)
{
    const float* x    = (const float*)d_in[0];
    const float* wq   = (const float*)d_in[1];
    const float* wk   = (const float*)d_in[2];
    const float* wv   = (const float*)d_in[3];
    const float* wo   = (const float*)d_in[4];
    const float* cosp = (const float*)d_in[5];
    const float* sinp = (const float*)d_in[6];

    unsigned short *xhi, *xlo, *wqkvThi, *wqkvTlo, *woThi, *woTlo, *atthi, *attlo;
    float *qkv, *att;
    cudaGetSymbolAddress((void**)&xhi, g_xhi);
    cudaGetSymbolAddress((void**)&xlo, g_xlo);
    cudaGetSymbolAddress((void**)&wqkvThi, g_wqkvT_hi);
    cudaGetSymbolAddress((void**)&wqkvTlo, g_wqkvT_lo);
    cudaGetSymbolAddress((void**)&woThi, g_woT_hi);
    cudaGetSymbolAddress((void**)&woTlo, g_woT_lo);
    cudaGetSymbolAddress((void**)&atthi, g_atthi);
    cudaGetSymbolAddress((void**)&attlo, g_attlo);
    cudaGetSymbolAddress((void**)&qkv, g_qkv);
    cudaGetSymbolAddress((void**)&att, g_att);

    cudaFuncSetAttribute(gemm_mma_kernel, cudaFuncAttributeMaxDynamicSharedMemorySize, GT_SMEM);
    cudaFuncSetAttribute(attn_kernel, cudaFuncAttributeMaxDynamicSharedMemorySize, ATT_SMEM_BYTES);

    // 1) Split x into bf16 hi/lo
    {
        int n4 = S_LEN * D_MODEL / 4;
        split_kernel<<<(n4 + 255) / 256, 256>>>(x, xhi, xlo, n4);
    }

    // 2) Transpose+split weights into concatenated [6144 x 4096] (wq|wk|wv)
    {
        dim3 tb(32, 8);
        split_transpose_kernel<<<dim3(D_MODEL / 32, D_MODEL / 32), tb>>>(
            wq, wqkvThi, wqkvTlo, D_MODEL, D_MODEL);
        split_transpose_kernel<<<dim3(1024 / 32, D_MODEL / 32), tb>>>(
            wk, wqkvThi + (size_t)4096 * D_MODEL, wqkvTlo + (size_t)4096 * D_MODEL,
            D_MODEL, 1024);
        split_transpose_kernel<<<dim3(1024 / 32, D_MODEL / 32), tb>>>(
            wv, wqkvThi + (size_t)5120 * D_MODEL, wqkvTlo + (size_t)5120 * D_MODEL,
            D_MODEL, 1024);
    }

    // 3) Fused QKV projection: [2048 x 6144] = x @ [wq|wk|wv]^T-major
    gemm_mma_kernel<<<dim3(S_LEN / GT_BM, QKV_N / GT_BN), 256, GT_SMEM>>>(
        xhi, xlo, wqkvThi, wqkvTlo, qkv, S_LEN, QKV_N, D_MODEL);

    // 4) RoPE on Q and K (in place inside qkv)
    {
        int totq = S_LEN * N_HEADS * 64;
        rope_kernel<<<(totq + 255) / 256, 256>>>(qkv, cosp, sinp, totq, N_HEADS, QKV_N);
        int totk = S_LEN * N_KV_HEADS * 64;
        rope_kernel<<<(totk + 255) / 256, 256>>>(qkv + 4096, cosp, sinp, totk, N_KV_HEADS, QKV_N);
    }

    // 5) Flash attention
    attn_kernel<<<dim3(S_LEN / 64, N_HEADS), 256, ATT_SMEM_BYTES>>>(qkv, att);

    // 6) Split attention output, transpose+split wo
    {
        int n4 = S_LEN * D_MODEL / 4;
        split_kernel<<<(n4 + 255) / 256, 256>>>(att, atthi, attlo, n4);
        dim3 tb(32, 8);
        split_transpose_kernel<<<dim3(D_MODEL / 32, D_MODEL / 32), tb>>>(
            wo, woThi, woTlo, D_MODEL, D_MODEL);
    }

    // 7) Output projection -> d_out
    gemm_mma_kernel<<<dim3(S_LEN / GT_BM, D_MODEL / GT_BN), 256, GT_SMEM>>>(
        atthi, attlo, woThi, woTlo, (float*)d_out, S_LEN, D_MODEL, D_MODEL);
}

// round 4
// speedup vs baseline: 2.3695x; 1.3514x over previous
#include <cuda_runtime.h>
#include <cuda_bf16.h>
#include <math.h>
#include <stdint.h>

// ---------------------------------------------------------------------------
// Problem constants
// ---------------------------------------------------------------------------
#define S_LEN 2048
#define D_MODEL 4096
#define N_HEADS 32
#define N_KV_HEADS 8
#define HEAD_DIM 128
#define QKV_N 6144                       // 4096 + 1024 + 1024
#define QK_SCALE 0.08838834764831845f    // 1/sqrt(128)

// ---------------------------------------------------------------------------
// Scratch (device globals; allocation is forbidden)
// ---------------------------------------------------------------------------
__device__ unsigned short g_xhi[S_LEN * D_MODEL];
__device__ unsigned short g_xlo[S_LEN * D_MODEL];
__device__ unsigned short g_wqkvT_hi[QKV_N * D_MODEL];
__device__ unsigned short g_wqkvT_lo[QKV_N * D_MODEL];
__device__ unsigned short g_woT_hi[D_MODEL * D_MODEL];
__device__ unsigned short g_woT_lo[D_MODEL * D_MODEL];
__device__ float g_qkv[S_LEN * QKV_N];
__device__ unsigned short g_qhi[S_LEN * D_MODEL];
__device__ unsigned short g_qlo[S_LEN * D_MODEL];
__device__ unsigned short g_khi[S_LEN * 1024];
__device__ unsigned short g_klo[S_LEN * 1024];
__device__ unsigned short g_vthi[1024 * S_LEN];   // [dglob][s]
__device__ unsigned short g_vtlo[1024 * S_LEN];
__device__ unsigned short g_atthi[S_LEN * D_MODEL];
__device__ unsigned short g_attlo[S_LEN * D_MODEL];

// ---------------------------------------------------------------------------
// Baseline-PTX helpers (NO tcgen05/TMA — harness compiles for compute_103)
// ---------------------------------------------------------------------------
__device__ __forceinline__ uint32_t cvta_shared(const void* p) {
    return (uint32_t)__cvta_generic_to_shared(p);
}
__device__ __forceinline__ void cp16(uint32_t dst, const void* src) {
    asm volatile("cp.async.cg.shared.global [%0], [%1], 16;" :: "r"(dst), "l"(src) : "memory");
}
__device__ __forceinline__ void cp_commit() {
    asm volatile("cp.async.commit_group;" ::: "memory");
}
template <int N> __device__ __forceinline__ void cp_wait() {
    asm volatile("cp.async.wait_group %0;" :: "n"(N) : "memory");
}
__device__ __forceinline__ void ldsm4(uint32_t* r, uint32_t addr) {
    asm volatile("ldmatrix.sync.aligned.m8n8.x4.shared.b16 {%0,%1,%2,%3}, [%4];"
                 : "=r"(r[0]), "=r"(r[1]), "=r"(r[2]), "=r"(r[3]) : "r"(addr));
}
__device__ __forceinline__ void mma_bf16(float* c, const uint32_t* a, const uint32_t* b) {
    asm volatile(
        "mma.sync.aligned.m16n8k16.row.col.f32.bf16.bf16.f32 "
        "{%0,%1,%2,%3}, {%4,%5,%6,%7}, {%8,%9}, {%0,%1,%2,%3};"
        : "+f"(c[0]), "+f"(c[1]), "+f"(c[2]), "+f"(c[3])
        : "r"(a[0]), "r"(a[1]), "r"(a[2]), "r"(a[3]), "r"(b[0]), "r"(b[1]));
}
__device__ __forceinline__ uint32_t pack_bf2(float lo, float hi) {
    __nv_bfloat162 h = __floats2bfloat162_rn(lo, hi);
    return *(uint32_t*)&h;
}

// ---------------------------------------------------------------------------
// fp32 -> bf16 hi/lo split (elementwise, vectorized)
// ---------------------------------------------------------------------------
__global__ void split_kernel(const float* __restrict__ x,
                             unsigned short* __restrict__ hi,
                             unsigned short* __restrict__ lo, int n4) {
    int i = blockIdx.x * blockDim.x + threadIdx.x;
    if (i >= n4) return;
    float4 v = ((const float4*)x)[i];
    __nv_bfloat16 h0 = __float2bfloat16(v.x);
    __nv_bfloat16 h1 = __float2bfloat16(v.y);
    __nv_bfloat16 h2 = __float2bfloat16(v.z);
    __nv_bfloat16 h3 = __float2bfloat16(v.w);
    ushort4 hh;
    hh.x = __bfloat16_as_ushort(h0); hh.y = __bfloat16_as_ushort(h1);
    hh.z = __bfloat16_as_ushort(h2); hh.w = __bfloat16_as_ushort(h3);
    ushort4 ll;
    ll.x = __bfloat16_as_ushort(__float2bfloat16(v.x - __bfloat162float(h0)));
    ll.y = __bfloat16_as_ushort(__float2bfloat16(v.y - __bfloat162float(h1)));
    ll.z = __bfloat16_as_ushort(__float2bfloat16(v.z - __bfloat162float(h2)));
    ll.w = __bfloat16_as_ushort(__float2bfloat16(v.w - __bfloat162float(h3)));
    ((ushort4*)hi)[i] = hh;
    ((ushort4*)lo)[i] = ll;
}

// ---------------------------------------------------------------------------
// W[K x N] fp32 -> T[N x K] bf16 hi/lo (tiled transpose + split)
// ---------------------------------------------------------------------------
__global__ void split_transpose_kernel(const float* __restrict__ W,
                                       unsigned short* __restrict__ Thi,
                                       unsigned short* __restrict__ Tlo,
                                       int K, int N) {
    __shared__ float t[32][33];
    int n0 = blockIdx.x * 32, k0 = blockIdx.y * 32;
    int tx = threadIdx.x, ty = threadIdx.y;  // 32 x 8
#pragma unroll
    for (int r = 0; r < 32; r += 8)
        t[ty + r][tx] = W[(size_t)(k0 + ty + r) * N + n0 + tx];
    __syncthreads();
#pragma unroll
    for (int r = 0; r < 32; r += 8) {
        float v = t[tx][ty + r];
        __nv_bfloat16 h = __float2bfloat16(v);
        float lv = v - __bfloat162float(h);
        size_t o = (size_t)(n0 + ty + r) * K + k0 + tx;
        Thi[o] = __bfloat16_as_ushort(h);
        Tlo[o] = __bfloat16_as_ushort(__float2bfloat16(lv));
    }
}

// ---------------------------------------------------------------------------
// V region of qkv (fp32, [s][1024] at col 5120, stride 6144) -> transposed
// bf16 hi/lo [dglob][s]
// ---------------------------------------------------------------------------
__global__ void vsplit_transpose_kernel(const float* __restrict__ qkv,
                                        unsigned short* __restrict__ Thi,
                                        unsigned short* __restrict__ Tlo) {
    __shared__ float t[32][33];
    int d0 = blockIdx.x * 32, s0 = blockIdx.y * 32;
    int tx = threadIdx.x, ty = threadIdx.y;  // 32 x 8
#pragma unroll
    for (int r = 0; r < 32; r += 8)
        t[ty + r][tx] = qkv[(size_t)(s0 + ty + r) * QKV_N + 5120 + d0 + tx];
    __syncthreads();
#pragma unroll
    for (int r = 0; r < 32; r += 8) {
        float v = t[tx][ty + r];
        __nv_bfloat16 h = __float2bfloat16(v);
        float lv = v - __bfloat162float(h);
        size_t o = (size_t)(d0 + ty + r) * S_LEN + s0 + tx;
        Thi[o] = __bfloat16_as_ushort(h);
        Tlo[o] = __bfloat16_as_ushort(__float2bfloat16(lv));
    }
}

// ---------------------------------------------------------------------------
// RoPE + scale + bf16 hi/lo split for Q and K regions of qkv.
// One thread per rotated pair. Pairs 0..2047 -> Q, 2048..2559 -> K.
// ---------------------------------------------------------------------------
__global__ void rope_split_kernel(const float* __restrict__ qkv,
                                  const float* __restrict__ cosp,
                                  const float* __restrict__ sinp,
                                  unsigned short* __restrict__ qhi,
                                  unsigned short* __restrict__ qlo,
                                  unsigned short* __restrict__ khi,
                                  unsigned short* __restrict__ klo) {
    int idx = blockIdx.x * blockDim.x + threadIdx.x;
    const int PAIRS = (D_MODEL + 1024) / 2;  // 2560 per row
    if (idx >= S_LEN * PAIRS) return;
    int s = idx / PAIRS;
    int pair = idx - s * PAIRS;
    int p = pair & 63;
    float c = cosp[s * 64 + p];
    float sn = sinp[s * 64 + p];
    bool isQ = pair < 2048;
    int col = isQ ? 2 * pair : 4096 + 2 * (pair - 2048);
    const float* src = qkv + (size_t)s * QKV_N + col;
    float t0 = src[0], t1 = src[1];
    float o0 = t0 * c - t1 * sn;
    float o1 = t0 * sn + t1 * c;
    if (isQ) { o0 *= QK_SCALE; o1 *= QK_SCALE; }
    __nv_bfloat16 h0 = __float2bfloat16(o0);
    __nv_bfloat16 h1 = __float2bfloat16(o1);
    ushort2 hh = make_ushort2(__bfloat16_as_ushort(h0), __bfloat16_as_ushort(h1));
    ushort2 ll = make_ushort2(
        __bfloat16_as_ushort(__float2bfloat16(o0 - __bfloat162float(h0))),
        __bfloat16_as_ushort(__float2bfloat16(o1 - __bfloat162float(h1))));
    if (isQ) {
        size_t o = (size_t)s * D_MODEL + 2 * pair;
        *(ushort2*)(qhi + o) = hh;
        *(ushort2*)(qlo + o) = ll;
    } else {
        size_t o = (size_t)s * 1024 + 2 * (pair - 2048);
        *(ushort2*)(khi + o) = hh;
        *(ushort2*)(klo + o) = ll;
    }
}

// ---------------------------------------------------------------------------
// Warp-MMA split-bf16 GEMM: C[M,N] = (Ahi+Alo)[M,K] @ (BThi+BTlo)[N,K]^T
// (unchanged from R3 — passing at ~344 TF/s effective)
// ---------------------------------------------------------------------------
#define GT_BM 128
#define GT_BN 128
#define GT_BK 32
#define GT_ROWB 80
#define GT_TILE 10240
#define GT_STAGE 40960
#define GT_STAGES 3
#define GT_SMEM (GT_STAGES * GT_STAGE)

__global__ __launch_bounds__(256) void gemm_mma_kernel(
    const unsigned short* __restrict__ Ahi_, const unsigned short* __restrict__ Alo_,
    const unsigned short* __restrict__ Bhi_, const unsigned short* __restrict__ Blo_,
    float* __restrict__ C, int M, int N, int K)
{
    extern __shared__ char smem[];
    uint32_t sb = cvta_shared(smem);
    const int tid = threadIdx.x;
    const int lane = tid & 31, wid = tid >> 5;
    const int warp_m = wid & 3;
    const int warp_n = wid >> 2;
    const int m0 = blockIdx.x * GT_BM;
    const int n0 = blockIdx.y * GT_BN;

    const unsigned short* srcs[4] = {
        Ahi_ + (size_t)m0 * K, Alo_ + (size_t)m0 * K,
        Bhi_ + (size_t)n0 * K, Blo_ + (size_t)n0 * K };

    auto load_stage = [&](int ch, int st) {
        uint32_t base = sb + st * GT_STAGE;
        int k0 = ch * GT_BK;
#pragma unroll
        for (int v = 0; v < 4; v++) {
            uint32_t tb = base + v * GT_TILE;
            const unsigned short* src = srcs[v];
            for (int i = tid; i < 512; i += 256) {
                int row = i >> 2, c = i & 3;
                cp16(tb + row * GT_ROWB + c * 16,
                     src + (size_t)row * K + k0 + c * 8);
            }
        }
        cp_commit();
    };

    float acc[2][8][4];
#pragma unroll
    for (int mt = 0; mt < 2; mt++)
#pragma unroll
        for (int nt = 0; nt < 8; nt++)
#pragma unroll
            for (int r = 0; r < 4; r++) acc[mt][nt][r] = 0.f;

    const int NC = K / GT_BK;
    load_stage(0, 0);
    load_stage(1, 1);

    const uint32_t a_off = (uint32_t)((lane & 15) * GT_ROWB + (lane >> 4) * 16);

    for (int ch = 0; ch < NC; ch++) {
        int st = ch % GT_STAGES;
        if (ch + 2 < NC) { load_stage(ch + 2, (ch + 2) % GT_STAGES); cp_wait<2>(); }
        else if (ch + 1 < NC) { cp_wait<1>(); }
        else { cp_wait<0>(); }
        __syncthreads();

        uint32_t base = sb + st * GT_STAGE;
        uint32_t aHi = base + (warp_m * 32) * GT_ROWB + a_off;
        uint32_t aLo = aHi + GT_TILE;
        uint32_t bHi = base + 2 * GT_TILE + (warp_n * 64) * GT_ROWB + a_off;
        uint32_t bLo = bHi + GT_TILE;

#pragma unroll
        for (int k16 = 0; k16 < 2; k16++) {
            uint32_t koff = k16 * 32;
            uint32_t ahi[2][4], alo[2][4];
#pragma unroll
            for (int mt = 0; mt < 2; mt++) {
                ldsm4(ahi[mt], aHi + mt * 16 * GT_ROWB + koff);
                ldsm4(alo[mt], aLo + mt * 16 * GT_ROWB + koff);
            }
            uint32_t bh[8][2], bl[8][2];
#pragma unroll
            for (int ng = 0; ng < 4; ng++) {
                uint32_t r[4];
                ldsm4(r, bHi + ng * 16 * GT_ROWB + koff);
                bh[2 * ng][0] = r[0]; bh[2 * ng][1] = r[2];
                bh[2 * ng + 1][0] = r[1]; bh[2 * ng + 1][1] = r[3];
                ldsm4(r, bLo + ng * 16 * GT_ROWB + koff);
                bl[2 * ng][0] = r[0]; bl[2 * ng][1] = r[2];
                bl[2 * ng + 1][0] = r[1]; bl[2 * ng + 1][1] = r[3];
            }
#pragma unroll
            for (int mt = 0; mt < 2; mt++)
#pragma unroll
                for (int nt = 0; nt < 8; nt++) {
                    mma_bf16(acc[mt][nt], ahi[mt], bh[nt]);
                    mma_bf16(acc[mt][nt], alo[mt], bh[nt]);
                    mma_bf16(acc[mt][nt], ahi[mt], bl[nt]);
                }
        }
        __syncthreads();
    }

#pragma unroll
    for (int mt = 0; mt < 2; mt++) {
        int row = m0 + warp_m * 32 + mt * 16 + (lane >> 2);
#pragma unroll
        for (int nt = 0; nt < 8; nt++) {
            int col = n0 + warp_n * 64 + nt * 8 + (lane & 3) * 2;
            *(float2*)&C[(size_t)row * N + col] =
                make_float2(acc[mt][nt][0], acc[mt][nt][1]);
            *(float2*)&C[(size_t)(row + 8) * N + col] =
                make_float2(acc[mt][nt][2], acc[mt][nt][3]);
        }
    }
}

// ---------------------------------------------------------------------------
// Tensor-core flash attention (causal, GQA 4:1), split-bf16, 3 passes.
// CTA: 128 q rows x 1 head, 8 warps (16 rows each), kv tile = 64.
// Q: [s][4096] bf16 hi/lo (pre-roped, pre-scaled); K: [s][1024] hi/lo;
// Vt: [dglob][s] hi/lo. Output: att bf16 hi/lo [s][4096].
// ---------------------------------------------------------------------------
#define AT_QROW 272      // 128 halfs * 2B + 16B pad
#define AT_VROW 144      // 64 halfs * 2B + 16B pad
#define AT_SQHI 0
#define AT_SQLO 34816
#define AT_STAGE0 69632
#define AT_KHI 0
#define AT_KLO 17408
#define AT_VHI 34816
#define AT_VLO 53248
#define AT_STAGE_SZ 71680
#define AT_SMEM (AT_STAGE0 + 2 * AT_STAGE_SZ)   // 212992 B

__global__ __launch_bounds__(256, 1) void attn_mma_kernel(
    const unsigned short* __restrict__ Qhi, const unsigned short* __restrict__ Qlo,
    const unsigned short* __restrict__ Khi, const unsigned short* __restrict__ Klo,
    const unsigned short* __restrict__ Vthi, const unsigned short* __restrict__ Vtlo,
    unsigned short* __restrict__ atthi, unsigned short* __restrict__ attlo)
{
    extern __shared__ char smem[];
    uint32_t sb = cvta_shared(smem);
    const int tid = threadIdx.x;
    const int lane = tid & 31, wid = tid >> 5;
    const int qblk = gridDim.x - 1 - blockIdx.x;   // heavy blocks first
    const int h = blockIdx.y;
    const int kvh = h >> 2;
    const int q0 = qblk * 128;
    const int wr = wid * 16;
    const int g = lane >> 2;       // row within m16 frag
    const int t4 = lane & 3;

    // ---- issue Q tile loads (once) ----
    {
        const unsigned short* qsrc[2] = {
            Qhi + (size_t)q0 * D_MODEL + h * 128,
            Qlo + (size_t)q0 * D_MODEL + h * 128 };
#pragma unroll
        for (int v = 0; v < 2; v++) {
            uint32_t dst = sb + (v ? AT_SQLO : AT_SQHI);
            for (int i = tid; i < 2048; i += 256) {
                int row = i >> 4, c = i & 15;
                cp16(dst + row * AT_QROW + c * 16,
                     qsrc[v] + (size_t)row * D_MODEL + c * 8);
            }
        }
        cp_commit();
    }

    const unsigned short* ksrc[2] = {
        Khi + kvh * 128, Klo + kvh * 128 };
    const unsigned short* vsrc[2] = {
        Vthi + (size_t)kvh * 128 * S_LEN, Vtlo + (size_t)kvh * 128 * S_LEN };

    auto load_tile = [&](int j, int st) {
        uint32_t base = sb + AT_STAGE0 + st * AT_STAGE_SZ;
        int kv0 = j * 64;
#pragma unroll
        for (int v = 0; v < 2; v++) {
            uint32_t kd = base + (v ? AT_KLO : AT_KHI);
            for (int i = tid; i < 1024; i += 256) {
                int row = i >> 4, c = i & 15;
                cp16(kd + row * AT_QROW + c * 16,
                     ksrc[v] + (size_t)(kv0 + row) * 1024 + c * 8);
            }
            uint32_t vd = base + (v ? AT_VLO : AT_VHI);
            for (int i = tid; i < 1024; i += 256) {
                int row = i >> 3, c = i & 7;
                cp16(vd + row * AT_VROW + c * 16,
                     vsrc[v] + (size_t)row * S_LEN + kv0 + c * 8);
            }
        }
        cp_commit();
    };

    const int ntiles = 2 * qblk + 2;
    load_tile(0, 0);
    cp_wait<1>();          // Q tile done
    __syncthreads();

    // ---- hoist Q fragments into registers ----
    const uint32_t lmoff = (uint32_t)((lane & 15) * AT_QROW + (lane >> 4) * 16);
    uint32_t aqh[8][4], aql[8][4];
    {
        uint32_t qh = sb + AT_SQHI + wr * AT_QROW + lmoff;
        uint32_t ql = sb + AT_SQLO + wr * AT_QROW + lmoff;
#pragma unroll
        for (int kk = 0; kk < 8; kk++) {
            ldsm4(aqh[kk], qh + kk * 32);
            ldsm4(aql[kk], ql + kk * 32);
        }
    }

    float o[16][4];
#pragma unroll
    for (int nt = 0; nt < 16; nt++)
#pragma unroll
        for (int r = 0; r < 4; r++) o[nt][r] = 0.f;
    float m0 = -1e30f, m1 = -1e30f, l0 = 0.f, l1 = 0.f;

    const uint32_t vmoff = (uint32_t)((lane & 15) * AT_VROW + (lane >> 4) * 16);

    for (int j = 0; j < ntiles; j++) {
        int st = j & 1;
        __syncthreads();   // protect st^1 buffer (compute j-1 done)
        if (j + 1 < ntiles) { load_tile(j + 1, st ^ 1); cp_wait<1>(); }
        else { cp_wait<0>(); }
        __syncthreads();

        uint32_t base = sb + AT_STAGE0 + st * AT_STAGE_SZ;
        uint32_t kHi = base + AT_KHI + lmoff;
        uint32_t kLo = base + AT_KLO + lmoff;

        // ---- S = Q @ K^T (3-pass split) ----
        float sacc[8][4];
#pragma unroll
        for (int nt = 0; nt < 8; nt++)
#pragma unroll
            for (int r = 0; r < 4; r++) sacc[nt][r] = 0.f;

#pragma unroll
        for (int kk = 0; kk < 8; kk++) {
#pragma unroll
            for (int ng = 0; ng < 4; ng++) {
                uint32_t rh[4], rl[4];
                ldsm4(rh, kHi + ng * 16 * AT_QROW + kk * 32);
                ldsm4(rl, kLo + ng * 16 * AT_QROW + kk * 32);
                uint32_t b0h[2] = { rh[0], rh[2] }, b1h[2] = { rh[1], rh[3] };
                uint32_t b0l[2] = { rl[0], rl[2] }, b1l[2] = { rl[1], rl[3] };
                mma_bf16(sacc[2 * ng],     aqh[kk], b0h);
                mma_bf16(sacc[2 * ng],     aql[kk], b0h);
                mma_bf16(sacc[2 * ng],     aqh[kk], b0l);
                mma_bf16(sacc[2 * ng + 1], aqh[kk], b1h);
                mma_bf16(sacc[2 * ng + 1], aql[kk], b1h);
                mma_bf16(sacc[2 * ng + 1], aqh[kk], b1l);
            }
        }

        // ---- causal mask (diagonal tiles only) ----
        if (j >= 2 * qblk) {
            int r0 = q0 + wr + g, r1 = r0 + 8;
            int cb = j * 64 + 2 * t4;
#pragma unroll
            for (int nt = 0; nt < 8; nt++) {
                int c0 = cb + nt * 8, c1 = c0 + 1;
                if (c0 > r0) sacc[nt][0] = -1e30f;
                if (c1 > r0) sacc[nt][1] = -1e30f;
                if (c0 > r1) sacc[nt][2] = -1e30f;
                if (c1 > r1) sacc[nt][3] = -1e30f;
            }
        }

        // ---- online softmax ----
        float mx0 = -1e30f, mx1 = -1e30f;
#pragma unroll
        for (int nt = 0; nt < 8; nt++) {
            mx0 = fmaxf(mx0, fmaxf(sacc[nt][0], sacc[nt][1]));
            mx1 = fmaxf(mx1, fmaxf(sacc[nt][2], sacc[nt][3]));
        }
        mx0 = fmaxf(mx0, __shfl_xor_sync(0xffffffffu, mx0, 1));
        mx0 = fmaxf(mx0, __shfl_xor_sync(0xffffffffu, mx0, 2));
        mx1 = fmaxf(mx1, __shfl_xor_sync(0xffffffffu, mx1, 1));
        mx1 = fmaxf(mx1, __shfl_xor_sync(0xffffffffu, mx1, 2));
        float mn0 = fmaxf(m0, mx0), mn1 = fmaxf(m1, mx1);
        float sc0 = __expf(m0 - mn0), sc1 = __expf(m1 - mn1);
        m0 = mn0; m1 = mn1;
        float sum0 = 0.f, sum1 = 0.f;
#pragma unroll
        for (int nt = 0; nt < 8; nt++) {
            sacc[nt][0] = __expf(sacc[nt][0] - mn0);
            sacc[nt][1] = __expf(sacc[nt][1] - mn0);
            sacc[nt][2] = __expf(sacc[nt][2] - mn1);
            sacc[nt][3] = __expf(sacc[nt][3] - mn1);
            sum0 += sacc[nt][0] + sacc[nt][1];
            sum1 += sacc[nt][2] + sacc[nt][3];
        }
        sum0 += __shfl_xor_sync(0xffffffffu, sum0, 1);
        sum0 += __shfl_xor_sync(0xffffffffu, sum0, 2);
        sum1 += __shfl_xor_sync(0xffffffffu, sum1, 1);
        sum1 += __shfl_xor_sync(0xffffffffu, sum1, 2);
        l0 = l0 * sc0 + sum0;
        l1 = l1 * sc1 + sum1;
#pragma unroll
        for (int nt = 0; nt < 16; nt++) {
            o[nt][0] *= sc0; o[nt][1] *= sc0;
            o[nt][2] *= sc1; o[nt][3] *= sc1;
        }

        // ---- O += P @ V (3-pass split) ----
        uint32_t vHi = base + AT_VHI + vmoff;
        uint32_t vLo = base + AT_VLO + vmoff;
#pragma unroll
        for (int kk2 = 0; kk2 < 4; kk2++) {
            // P fragments from S accumulators (C->A layout identity)
            float p00 = sacc[2 * kk2][0],     p01 = sacc[2 * kk2][1];
            float p02 = sacc[2 * kk2][2],     p03 = sacc[2 * kk2][3];
            float p10 = sacc[2 * kk2 + 1][0], p11 = sacc[2 * kk2 + 1][1];
            float p12 = sacc[2 * kk2 + 1][2], p13 = sacc[2 * kk2 + 1][3];
            uint32_t aph[4], apl[4];
            aph[0] = pack_bf2(p00, p01);
            aph[1] = pack_bf2(p02, p03);
            aph[2] = pack_bf2(p10, p11);
            aph[3] = pack_bf2(p12, p13);
            __nv_bfloat162* hp = (__nv_bfloat162*)aph;
            apl[0] = pack_bf2(p00 - __bfloat162float(hp[0].x), p01 - __bfloat162float(hp[0].y));
            apl[1] = pack_bf2(p02 - __bfloat162float(hp[1].x), p03 - __bfloat162float(hp[1].y));
            apl[2] = pack_bf2(p10 - __bfloat162float(hp[2].x), p11 - __bfloat162float(hp[2].y));
            apl[3] = pack_bf2(p12 - __bfloat162float(hp[3].x), p13 - __bfloat162float(hp[3].y));
#pragma unroll
            for (int ng = 0; ng < 8; ng++) {
                uint32_t rv[4];
                ldsm4(rv, vHi + ng * 16 * AT_VROW + kk2 * 32);
                uint32_t b0[2] = { rv[0], rv[2] }, b1[2] = { rv[1], rv[3] };
                mma_bf16(o[2 * ng],     aph, b0);
                mma_bf16(o[2 * ng + 1], aph, b1);
                mma_bf16(o[2 * ng],     apl, b0);
                mma_bf16(o[2 * ng + 1], apl, b1);
                ldsm4(rv, vLo + ng * 16 * AT_VROW + kk2 * 32);
                uint32_t c0[2] = { rv[0], rv[2] }, c1[2] = { rv[1], rv[3] };
                mma_bf16(o[2 * ng],     aph, c0);
                mma_bf16(o[2 * ng + 1], aph, c1);
            }
        }
    }

    // ---- finalize: O /= l, write bf16 hi/lo ----
    float inv0 = 1.f / l0, inv1 = 1.f / l1;
    int row0 = q0 + wr + g;
    size_t ob0 = (size_t)row0 * D_MODEL + h * 128 + 2 * t4;
    size_t ob1 = (size_t)(row0 + 8) * D_MODEL + h * 128 + 2 * t4;
#pragma unroll
    for (int nt = 0; nt < 16; nt++) {
        float v0 = o[nt][0] * inv0, v1 = o[nt][1] * inv0;
        float v2 = o[nt][2] * inv1, v3 = o[nt][3] * inv1;
        __nv_bfloat162 h01 = __floats2bfloat162_rn(v0, v1);
        __nv_bfloat162 h23 = __floats2bfloat162_rn(v2, v3);
        ushort2 hh0 = make_ushort2(__bfloat16_as_ushort(h01.x), __bfloat16_as_ushort(h01.y));
        ushort2 hh1 = make_ushort2(__bfloat16_as_ushort(h23.x), __bfloat16_as_ushort(h23.y));
        ushort2 ll0 = make_ushort2(
            __bfloat16_as_ushort(__float2bfloat16(v0 - __bfloat162float(h01.x))),
            __bfloat16_as_ushort(__float2bfloat16(v1 - __bfloat162float(h01.y))));
        ushort2 ll1 = make_ushort2(
            __bfloat16_as_ushort(__float2bfloat16(v2 - __bfloat162float(h23.x))),
            __bfloat16_as_ushort(__float2bfloat16(v3 - __bfloat162float(h23.y))));
        *(ushort2*)(atthi + ob0 + nt * 8) = hh0;
        *(ushort2*)(attlo + ob0 + nt * 8) = ll0;
        *(ushort2*)(atthi + ob1 + nt * 8) = hh1;
        *(ushort2*)(attlo + ob1 + nt * 8) = ll1;
    }
}

// ---------------------------------------------------------------------------
// Launch
// inputs: 0:x 1:wq 2:wk 3:wv 4:wo 5:freqs_cos 6:freqs_sin 7:mask 8:start_pos 9:init_seqlen
// ---------------------------------------------------------------------------
extern "C" void kernel_launch(void* const* d_in, const int* in_sizes, int n_in,
                              void* d_out, int out_size)
{
    const float* x    = (const float*)d_in[0];
    const float* wq   = (const float*)d_in[1];
    const float* wk   = (const float*)d_in[2];
    const float* wv   = (const float*)d_in[3];
    const float* wo   = (const float*)d_in[4];
    const float* cosp = (const float*)d_in[5];
    const float* sinp = (const float*)d_in[6];

    unsigned short *xhi, *xlo, *wqkvThi, *wqkvTlo, *woThi, *woTlo;
    unsigned short *qhi, *qlo, *khi, *klo, *vthi, *vtlo, *atthi, *attlo;
    float *qkv;
    cudaGetSymbolAddress((void**)&xhi, g_xhi);
    cudaGetSymbolAddress((void**)&xlo, g_xlo);
    cudaGetSymbolAddress((void**)&wqkvThi, g_wqkvT_hi);
    cudaGetSymbolAddress((void**)&wqkvTlo, g_wqkvT_lo);
    cudaGetSymbolAddress((void**)&woThi, g_woT_hi);
    cudaGetSymbolAddress((void**)&woTlo, g_woT_lo);
    cudaGetSymbolAddress((void**)&qhi, g_qhi);
    cudaGetSymbolAddress((void**)&qlo, g_qlo);
    cudaGetSymbolAddress((void**)&khi, g_khi);
    cudaGetSymbolAddress((void**)&klo, g_klo);
    cudaGetSymbolAddress((void**)&vthi, g_vthi);
    cudaGetSymbolAddress((void**)&vtlo, g_vtlo);
    cudaGetSymbolAddress((void**)&atthi, g_atthi);
    cudaGetSymbolAddress((void**)&attlo, g_attlo);
    cudaGetSymbolAddress((void**)&qkv, g_qkv);

    cudaFuncSetAttribute(gemm_mma_kernel, cudaFuncAttributeMaxDynamicSharedMemorySize, GT_SMEM);
    cudaFuncSetAttribute(attn_mma_kernel, cudaFuncAttributeMaxDynamicSharedMemorySize, AT_SMEM);

    // 1) Split x into bf16 hi/lo
    {
        int n4 = S_LEN * D_MODEL / 4;
        split_kernel<<<(n4 + 255) / 256, 256>>>(x, xhi, xlo, n4);
    }

    // 2) Transpose+split weights (wq|wk|wv concatenated, and wo)
    {
        dim3 tb(32, 8);
        split_transpose_kernel<<<dim3(D_MODEL / 32, D_MODEL / 32), tb>>>(
            wq, wqkvThi, wqkvTlo, D_MODEL, D_MODEL);
        split_transpose_kernel<<<dim3(1024 / 32, D_MODEL / 32), tb>>>(
            wk, wqkvThi + (size_t)4096 * D_MODEL, wqkvTlo + (size_t)4096 * D_MODEL,
            D_MODEL, 1024);
        split_transpose_kernel<<<dim3(1024 / 32, D_MODEL / 32), tb>>>(
            wv, wqkvThi + (size_t)5120 * D_MODEL, wqkvTlo + (size_t)5120 * D_MODEL,
            D_MODEL, 1024);
        split_transpose_kernel<<<dim3(D_MODEL / 32, D_MODEL / 32), tb>>>(
            wo, woThi, woTlo, D_MODEL, D_MODEL);
    }

    // 3) Fused QKV projection: [2048 x 6144]
    gemm_mma_kernel<<<dim3(S_LEN / GT_BM, QKV_N / GT_BN), 256, GT_SMEM>>>(
        xhi, xlo, wqkvThi, wqkvTlo, qkv, S_LEN, QKV_N, D_MODEL);

    // 4) RoPE + scale + split Q,K; transpose + split V
    {
        int tot = S_LEN * 2560;
        rope_split_kernel<<<(tot + 255) / 256, 256>>>(qkv, cosp, sinp,
                                                      qhi, qlo, khi, klo);
        dim3 tb(32, 8);
        vsplit_transpose_kernel<<<dim3(1024 / 32, S_LEN / 32), tb>>>(qkv, vthi, vtlo);
    }

    // 5) Tensor-core flash attention -> att bf16 hi/lo
    attn_mma_kernel<<<dim3(S_LEN / 128, N_HEADS), 256, AT_SMEM>>>(
        qhi, qlo, khi, klo, vthi, vtlo, atthi, attlo);

    // 6) Output projection -> d_out
    gemm_mma_kernel<<<dim3(S_LEN / GT_BM, D_MODEL / GT_BN), 256, GT_SMEM>>>(
        atthi, attlo, woThi, woTlo, (float*)d_out, S_LEN, D_MODEL, D_MODEL);
}

// round 5
// speedup vs baseline: 2.8204x; 1.1903x over previous
#include <cuda_runtime.h>
#include <cuda_bf16.h>
#include <math.h>
#include <stdint.h>

// ---------------------------------------------------------------------------
// Problem constants
// ---------------------------------------------------------------------------
#define S_LEN 2048
#define D_MODEL 4096
#define N_HEADS 32
#define N_KV_HEADS 8
#define HEAD_DIM 128
#define QKV_N 6144                       // 4096 + 1024 + 1024
#define QK_SCALE 0.08838834764831845f    // 1/sqrt(128)

// ---------------------------------------------------------------------------
// Scratch (device globals; allocation is forbidden)
// ---------------------------------------------------------------------------
__device__ unsigned short g_xhi[S_LEN * D_MODEL];
__device__ unsigned short g_xlo[S_LEN * D_MODEL];
__device__ unsigned short g_wqkvT_hi[QKV_N * D_MODEL];
__device__ unsigned short g_wqkvT_lo[QKV_N * D_MODEL];
__device__ unsigned short g_woT_hi[D_MODEL * D_MODEL];
__device__ unsigned short g_woT_lo[D_MODEL * D_MODEL];
__device__ float g_qkv[S_LEN * QKV_N];
__device__ unsigned short g_qhi[S_LEN * D_MODEL];
__device__ unsigned short g_qlo[S_LEN * D_MODEL];
__device__ unsigned short g_khi[S_LEN * 1024];
__device__ unsigned short g_klo[S_LEN * 1024];
__device__ unsigned short g_vthi[1024 * S_LEN];   // [dglob][s]
__device__ unsigned short g_vtlo[1024 * S_LEN];
__device__ unsigned short g_atthi[S_LEN * D_MODEL];
__device__ unsigned short g_attlo[S_LEN * D_MODEL];

// ---------------------------------------------------------------------------
// Baseline-PTX helpers (NO tcgen05/TMA — harness compiles for compute_103)
// ---------------------------------------------------------------------------
__device__ __forceinline__ uint32_t cvta_shared(const void* p) {
    return (uint32_t)__cvta_generic_to_shared(p);
}
__device__ __forceinline__ void cp16(uint32_t dst, const void* src) {
    asm volatile("cp.async.cg.shared.global [%0], [%1], 16;" :: "r"(dst), "l"(src) : "memory");
}
__device__ __forceinline__ void cp_commit() {
    asm volatile("cp.async.commit_group;" ::: "memory");
}
template <int N> __device__ __forceinline__ void cp_wait() {
    asm volatile("cp.async.wait_group %0;" :: "n"(N) : "memory");
}
__device__ __forceinline__ void ldsm4(uint32_t* r, uint32_t addr) {
    asm volatile("ldmatrix.sync.aligned.m8n8.x4.shared.b16 {%0,%1,%2,%3}, [%4];"
                 : "=r"(r[0]), "=r"(r[1]), "=r"(r[2]), "=r"(r[3]) : "r"(addr));
}
__device__ __forceinline__ void mma_bf16(float* c, const uint32_t* a, const uint32_t* b) {
    asm volatile(
        "mma.sync.aligned.m16n8k16.row.col.f32.bf16.bf16.f32 "
        "{%0,%1,%2,%3}, {%4,%5,%6,%7}, {%8,%9}, {%0,%1,%2,%3};"
        : "+f"(c[0]), "+f"(c[1]), "+f"(c[2]), "+f"(c[3])
        : "r"(a[0]), "r"(a[1]), "r"(a[2]), "r"(a[3]), "r"(b[0]), "r"(b[1]));
}
__device__ __forceinline__ uint32_t pack_bf2(float lo, float hi) {
    __nv_bfloat162 h = __floats2bfloat162_rn(lo, hi);
    return *(uint32_t*)&h;
}

// ---------------------------------------------------------------------------
// fp32 -> bf16 hi/lo split (elementwise, vectorized)
// ---------------------------------------------------------------------------
__global__ void split_kernel(const float* __restrict__ x,
                             unsigned short* __restrict__ hi,
                             unsigned short* __restrict__ lo, int n4) {
    int i = blockIdx.x * blockDim.x + threadIdx.x;
    if (i >= n4) return;
    float4 v = ((const float4*)x)[i];
    __nv_bfloat16 h0 = __float2bfloat16(v.x);
    __nv_bfloat16 h1 = __float2bfloat16(v.y);
    __nv_bfloat16 h2 = __float2bfloat16(v.z);
    __nv_bfloat16 h3 = __float2bfloat16(v.w);
    ushort4 hh;
    hh.x = __bfloat16_as_ushort(h0); hh.y = __bfloat16_as_ushort(h1);
    hh.z = __bfloat16_as_ushort(h2); hh.w = __bfloat16_as_ushort(h3);
    ushort4 ll;
    ll.x = __bfloat16_as_ushort(__float2bfloat16(v.x - __bfloat162float(h0)));
    ll.y = __bfloat16_as_ushort(__float2bfloat16(v.y - __bfloat162float(h1)));
    ll.z = __bfloat16_as_ushort(__float2bfloat16(v.z - __bfloat162float(h2)));
    ll.w = __bfloat16_as_ushort(__float2bfloat16(v.w - __bfloat162float(h3)));
    ((ushort4*)hi)[i] = hh;
    ((ushort4*)lo)[i] = ll;
}

// ---------------------------------------------------------------------------
// W[K x N] fp32 -> T[N x K] bf16 hi/lo (tiled transpose + split)
// ---------------------------------------------------------------------------
__global__ void split_transpose_kernel(const float* __restrict__ W,
                                       unsigned short* __restrict__ Thi,
                                       unsigned short* __restrict__ Tlo,
                                       int K, int N) {
    __shared__ float t[32][33];
    int n0 = blockIdx.x * 32, k0 = blockIdx.y * 32;
    int tx = threadIdx.x, ty = threadIdx.y;  // 32 x 8
#pragma unroll
    for (int r = 0; r < 32; r += 8)
        t[ty + r][tx] = W[(size_t)(k0 + ty + r) * N + n0 + tx];
    __syncthreads();
#pragma unroll
    for (int r = 0; r < 32; r += 8) {
        float v = t[tx][ty + r];
        __nv_bfloat16 h = __float2bfloat16(v);
        float lv = v - __bfloat162float(h);
        size_t o = (size_t)(n0 + ty + r) * K + k0 + tx;
        Thi[o] = __bfloat16_as_ushort(h);
        Tlo[o] = __bfloat16_as_ushort(__float2bfloat16(lv));
    }
}

// ---------------------------------------------------------------------------
// V region of qkv (fp32, [s][1024] at col 5120, stride 6144) -> transposed
// bf16 hi/lo [dglob][s]
// ---------------------------------------------------------------------------
__global__ void vsplit_transpose_kernel(const float* __restrict__ qkv,
                                        unsigned short* __restrict__ Thi,
                                        unsigned short* __restrict__ Tlo) {
    __shared__ float t[32][33];
    int d0 = blockIdx.x * 32, s0 = blockIdx.y * 32;
    int tx = threadIdx.x, ty = threadIdx.y;  // 32 x 8
#pragma unroll
    for (int r = 0; r < 32; r += 8)
        t[ty + r][tx] = qkv[(size_t)(s0 + ty + r) * QKV_N + 5120 + d0 + tx];
    __syncthreads();
#pragma unroll
    for (int r = 0; r < 32; r += 8) {
        float v = t[tx][ty + r];
        __nv_bfloat16 h = __float2bfloat16(v);
        float lv = v - __bfloat162float(h);
        size_t o = (size_t)(d0 + ty + r) * S_LEN + s0 + tx;
        Thi[o] = __bfloat16_as_ushort(h);
        Tlo[o] = __bfloat16_as_ushort(__float2bfloat16(lv));
    }
}

// ---------------------------------------------------------------------------
// RoPE + scale + bf16 hi/lo split for Q and K regions of qkv.
// ---------------------------------------------------------------------------
__global__ void rope_split_kernel(const float* __restrict__ qkv,
                                  const float* __restrict__ cosp,
                                  const float* __restrict__ sinp,
                                  unsigned short* __restrict__ qhi,
                                  unsigned short* __restrict__ qlo,
                                  unsigned short* __restrict__ khi,
                                  unsigned short* __restrict__ klo) {
    int idx = blockIdx.x * blockDim.x + threadIdx.x;
    const int PAIRS = (D_MODEL + 1024) / 2;  // 2560 per row
    if (idx >= S_LEN * PAIRS) return;
    int s = idx / PAIRS;
    int pair = idx - s * PAIRS;
    int p = pair & 63;
    float c = cosp[s * 64 + p];
    float sn = sinp[s * 64 + p];
    bool isQ = pair < 2048;
    int col = isQ ? 2 * pair : 4096 + 2 * (pair - 2048);
    const float* src = qkv + (size_t)s * QKV_N + col;
    float t0 = src[0], t1 = src[1];
    float o0 = t0 * c - t1 * sn;
    float o1 = t0 * sn + t1 * c;
    if (isQ) { o0 *= QK_SCALE; o1 *= QK_SCALE; }
    __nv_bfloat16 h0 = __float2bfloat16(o0);
    __nv_bfloat16 h1 = __float2bfloat16(o1);
    ushort2 hh = make_ushort2(__bfloat16_as_ushort(h0), __bfloat16_as_ushort(h1));
    ushort2 ll = make_ushort2(
        __bfloat16_as_ushort(__float2bfloat16(o0 - __bfloat162float(h0))),
        __bfloat16_as_ushort(__float2bfloat16(o1 - __bfloat162float(h1))));
    if (isQ) {
        size_t o = (size_t)s * D_MODEL + 2 * pair;
        *(ushort2*)(qhi + o) = hh;
        *(ushort2*)(qlo + o) = ll;
    } else {
        size_t o = (size_t)s * 1024 + 2 * (pair - 2048);
        *(ushort2*)(khi + o) = hh;
        *(ushort2*)(klo + o) = ll;
    }
}

// ---------------------------------------------------------------------------
// Warp-MMA split-bf16 GEMM: C[M,N] = (Ahi+Alo)[M,K] @ (BThi+BTlo)[N,K]^T
// CTA tile 128x128, BK=32, 8 warps (warp tile 32x64).
// R5: 2 stages (80KB smem) -> 2 CTAs/SM (16 warps) to fill HMMA issue bubbles.
// ---------------------------------------------------------------------------
#define GT_BM 128
#define GT_BN 128
#define GT_BK 32
#define GT_ROWB 80
#define GT_TILE 10240
#define GT_STAGE 40960
#define GT_STAGES 2
#define GT_SMEM (GT_STAGES * GT_STAGE)

__global__ __launch_bounds__(256, 2) void gemm_mma_kernel(
    const unsigned short* __restrict__ Ahi_, const unsigned short* __restrict__ Alo_,
    const unsigned short* __restrict__ Bhi_, const unsigned short* __restrict__ Blo_,
    float* __restrict__ C, int M, int N, int K)
{
    extern __shared__ char smem[];
    uint32_t sb = cvta_shared(smem);
    const int tid = threadIdx.x;
    const int lane = tid & 31, wid = tid >> 5;
    const int warp_m = wid & 3;
    const int warp_n = wid >> 2;
    const int m0 = blockIdx.x * GT_BM;
    const int n0 = blockIdx.y * GT_BN;

    const unsigned short* srcs[4] = {
        Ahi_ + (size_t)m0 * K, Alo_ + (size_t)m0 * K,
        Bhi_ + (size_t)n0 * K, Blo_ + (size_t)n0 * K };

    auto load_stage = [&](int ch, int st) {
        uint32_t base = sb + st * GT_STAGE;
        int k0 = ch * GT_BK;
#pragma unroll
        for (int v = 0; v < 4; v++) {
            uint32_t tb = base + v * GT_TILE;
            const unsigned short* src = srcs[v];
            for (int i = tid; i < 512; i += 256) {
                int row = i >> 2, c = i & 3;
                cp16(tb + row * GT_ROWB + c * 16,
                     src + (size_t)row * K + k0 + c * 8);
            }
        }
        cp_commit();
    };

    float acc[2][8][4];
#pragma unroll
    for (int mt = 0; mt < 2; mt++)
#pragma unroll
        for (int nt = 0; nt < 8; nt++)
#pragma unroll
            for (int r = 0; r < 4; r++) acc[mt][nt][r] = 0.f;

    const int NC = K / GT_BK;
    load_stage(0, 0);

    const uint32_t a_off = (uint32_t)((lane & 15) * GT_ROWB + (lane >> 4) * 16);

    for (int ch = 0; ch < NC; ch++) {
        int st = ch & 1;
        if (ch + 1 < NC) { load_stage(ch + 1, st ^ 1); cp_wait<1>(); }
        else { cp_wait<0>(); }
        __syncthreads();

        uint32_t base = sb + st * GT_STAGE;
        uint32_t aHi = base + (warp_m * 32) * GT_ROWB + a_off;
        uint32_t aLo = aHi + GT_TILE;
        uint32_t bHi = base + 2 * GT_TILE + (warp_n * 64) * GT_ROWB + a_off;
        uint32_t bLo = bHi + GT_TILE;

#pragma unroll
        for (int k16 = 0; k16 < 2; k16++) {
            uint32_t koff = k16 * 32;
            uint32_t ahi[2][4], alo[2][4];
#pragma unroll
            for (int mt = 0; mt < 2; mt++) {
                ldsm4(ahi[mt], aHi + mt * 16 * GT_ROWB + koff);
                ldsm4(alo[mt], aLo + mt * 16 * GT_ROWB + koff);
            }
            uint32_t bh[8][2], bl[8][2];
#pragma unroll
            for (int ng = 0; ng < 4; ng++) {
                uint32_t r[4];
                ldsm4(r, bHi + ng * 16 * GT_ROWB + koff);
                bh[2 * ng][0] = r[0]; bh[2 * ng][1] = r[2];
                bh[2 * ng + 1][0] = r[1]; bh[2 * ng + 1][1] = r[3];
                ldsm4(r, bLo + ng * 16 * GT_ROWB + koff);
                bl[2 * ng][0] = r[0]; bl[2 * ng][1] = r[2];
                bl[2 * ng + 1][0] = r[1]; bl[2 * ng + 1][1] = r[3];
            }
#pragma unroll
            for (int mt = 0; mt < 2; mt++)
#pragma unroll
                for (int nt = 0; nt < 8; nt++) {
                    mma_bf16(acc[mt][nt], ahi[mt], bh[nt]);
                    mma_bf16(acc[mt][nt], alo[mt], bh[nt]);
                    mma_bf16(acc[mt][nt], ahi[mt], bl[nt]);
                }
        }
        __syncthreads();
    }

#pragma unroll
    for (int mt = 0; mt < 2; mt++) {
        int row = m0 + warp_m * 32 + mt * 16 + (lane >> 2);
#pragma unroll
        for (int nt = 0; nt < 8; nt++) {
            int col = n0 + warp_n * 64 + nt * 8 + (lane & 3) * 2;
            *(float2*)&C[(size_t)row * N + col] =
                make_float2(acc[mt][nt][0], acc[mt][nt][1]);
            *(float2*)&C[(size_t)(row + 8) * N + col] =
                make_float2(acc[mt][nt][2], acc[mt][nt][3]);
        }
    }
}

// ---------------------------------------------------------------------------
// Tensor-core flash attention (causal, GQA 4:1), split-bf16, 3 passes.
// (unchanged from R4 — passing)
// ---------------------------------------------------------------------------
#define AT_QROW 272
#define AT_VROW 144
#define AT_SQHI 0
#define AT_SQLO 34816
#define AT_STAGE0 69632
#define AT_KHI 0
#define AT_KLO 17408
#define AT_VHI 34816
#define AT_VLO 53248
#define AT_STAGE_SZ 71680
#define AT_SMEM (AT_STAGE0 + 2 * AT_STAGE_SZ)   // 212992 B

__global__ __launch_bounds__(256, 1) void attn_mma_kernel(
    const unsigned short* __restrict__ Qhi, const unsigned short* __restrict__ Qlo,
    const unsigned short* __restrict__ Khi, const unsigned short* __restrict__ Klo,
    const unsigned short* __restrict__ Vthi, const unsigned short* __restrict__ Vtlo,
    unsigned short* __restrict__ atthi, unsigned short* __restrict__ attlo)
{
    extern __shared__ char smem[];
    uint32_t sb = cvta_shared(smem);
    const int tid = threadIdx.x;
    const int lane = tid & 31, wid = tid >> 5;
    const int qblk = gridDim.x - 1 - blockIdx.x;
    const int h = blockIdx.y;
    const int kvh = h >> 2;
    const int q0 = qblk * 128;
    const int wr = wid * 16;
    const int g = lane >> 2;
    const int t4 = lane & 3;

    {
        const unsigned short* qsrc[2] = {
            Qhi + (size_t)q0 * D_MODEL + h * 128,
            Qlo + (size_t)q0 * D_MODEL + h * 128 };
#pragma unroll
        for (int v = 0; v < 2; v++) {
            uint32_t dst = sb + (v ? AT_SQLO : AT_SQHI);
            for (int i = tid; i < 2048; i += 256) {
                int row = i >> 4, c = i & 15;
                cp16(dst + row * AT_QROW + c * 16,
                     qsrc[v] + (size_t)row * D_MODEL + c * 8);
            }
        }
        cp_commit();
    }

    const unsigned short* ksrc[2] = {
        Khi + kvh * 128, Klo + kvh * 128 };
    const unsigned short* vsrc[2] = {
        Vthi + (size_t)kvh * 128 * S_LEN, Vtlo + (size_t)kvh * 128 * S_LEN };

    auto load_tile = [&](int j, int st) {
        uint32_t base = sb + AT_STAGE0 + st * AT_STAGE_SZ;
        int kv0 = j * 64;
#pragma unroll
        for (int v = 0; v < 2; v++) {
            uint32_t kd = base + (v ? AT_KLO : AT_KHI);
            for (int i = tid; i < 1024; i += 256) {
                int row = i >> 4, c = i & 15;
                cp16(kd + row * AT_QROW + c * 16,
                     ksrc[v] + (size_t)(kv0 + row) * 1024 + c * 8);
            }
            uint32_t vd = base + (v ? AT_VLO : AT_VHI);
            for (int i = tid; i < 1024; i += 256) {
                int row = i >> 3, c = i & 7;
                cp16(vd + row * AT_VROW + c * 16,
                     vsrc[v] + (size_t)row * S_LEN + kv0 + c * 8);
            }
        }
        cp_commit();
    };

    const int ntiles = 2 * qblk + 2;
    load_tile(0, 0);
    cp_wait<1>();
    __syncthreads();

    const uint32_t lmoff = (uint32_t)((lane & 15) * AT_QROW + (lane >> 4) * 16);
    uint32_t aqh[8][4], aql[8][4];
    {
        uint32_t qh = sb + AT_SQHI + wr * AT_QROW + lmoff;
        uint32_t ql = sb + AT_SQLO + wr * AT_QROW + lmoff;
#pragma unroll
        for (int kk = 0; kk < 8; kk++) {
            ldsm4(aqh[kk], qh + kk * 32);
            ldsm4(aql[kk], ql + kk * 32);
        }
    }

    float o[16][4];
#pragma unroll
    for (int nt = 0; nt < 16; nt++)
#pragma unroll
        for (int r = 0; r < 4; r++) o[nt][r] = 0.f;
    float m0 = -1e30f, m1 = -1e30f, l0 = 0.f, l1 = 0.f;

    const uint32_t vmoff = (uint32_t)((lane & 15) * AT_VROW + (lane >> 4) * 16);

    for (int j = 0; j < ntiles; j++) {
        int st = j & 1;
        __syncthreads();
        if (j + 1 < ntiles) { load_tile(j + 1, st ^ 1); cp_wait<1>(); }
        else { cp_wait<0>(); }
        __syncthreads();

        uint32_t base = sb + AT_STAGE0 + st * AT_STAGE_SZ;
        uint32_t kHi = base + AT_KHI + lmoff;
        uint32_t kLo = base + AT_KLO + lmoff;

        float sacc[8][4];
#pragma unroll
        for (int nt = 0; nt < 8; nt++)
#pragma unroll
            for (int r = 0; r < 4; r++) sacc[nt][r] = 0.f;

#pragma unroll
        for (int kk = 0; kk < 8; kk++) {
#pragma unroll
            for (int ng = 0; ng < 4; ng++) {
                uint32_t rh[4], rl[4];
                ldsm4(rh, kHi + ng * 16 * AT_QROW + kk * 32);
                ldsm4(rl, kLo + ng * 16 * AT_QROW + kk * 32);
                uint32_t b0h[2] = { rh[0], rh[2] }, b1h[2] = { rh[1], rh[3] };
                uint32_t b0l[2] = { rl[0], rl[2] }, b1l[2] = { rl[1], rl[3] };
                mma_bf16(sacc[2 * ng],     aqh[kk], b0h);
                mma_bf16(sacc[2 * ng],     aql[kk], b0h);
                mma_bf16(sacc[2 * ng],     aqh[kk], b0l);
                mma_bf16(sacc[2 * ng + 1], aqh[kk], b1h);
                mma_bf16(sacc[2 * ng + 1], aql[kk], b1h);
                mma_bf16(sacc[2 * ng + 1], aqh[kk], b1l);
            }
        }

        if (j >= 2 * qblk) {
            int r0 = q0 + wr + g, r1 = r0 + 8;
            int cb = j * 64 + 2 * t4;
#pragma unroll
            for (int nt = 0; nt < 8; nt++) {
                int c0 = cb + nt * 8, c1 = c0 + 1;
                if (c0 > r0) sacc[nt][0] = -1e30f;
                if (c1 > r0) sacc[nt][1] = -1e30f;
                if (c0 > r1) sacc[nt][2] = -1e30f;
                if (c1 > r1) sacc[nt][3] = -1e30f;
            }
        }

        float mx0 = -1e30f, mx1 = -1e30f;
#pragma unroll
        for (int nt = 0; nt < 8; nt++) {
            mx0 = fmaxf(mx0, fmaxf(sacc[nt][0], sacc[nt][1]));
            mx1 = fmaxf(mx1, fmaxf(sacc[nt][2], sacc[nt][3]));
        }
        mx0 = fmaxf(mx0, __shfl_xor_sync(0xffffffffu, mx0, 1));
        mx0 = fmaxf(mx0, __shfl_xor_sync(0xffffffffu, mx0, 2));
        mx1 = fmaxf(mx1, __shfl_xor_sync(0xffffffffu, mx1, 1));
        mx1 = fmaxf(mx1, __shfl_xor_sync(0xffffffffu, mx1, 2));
        float mn0 = fmaxf(m0, mx0), mn1 = fmaxf(m1, mx1);
        float sc0 = __expf(m0 - mn0), sc1 = __expf(m1 - mn1);
        m0 = mn0; m1 = mn1;
        float sum0 = 0.f, sum1 = 0.f;
#pragma unroll
        for (int nt = 0; nt < 8; nt++) {
            sacc[nt][0] = __expf(sacc[nt][0] - mn0);
            sacc[nt][1] = __expf(sacc[nt][1] - mn0);
            sacc[nt][2] = __expf(sacc[nt][2] - mn1);
            sacc[nt][3] = __expf(sacc[nt][3] - mn1);
            sum0 += sacc[nt][0] + sacc[nt][1];
            sum1 += sacc[nt][2] + sacc[nt][3];
        }
        sum0 += __shfl_xor_sync(0xffffffffu, sum0, 1);
        sum0 += __shfl_xor_sync(0xffffffffu, sum0, 2);
        sum1 += __shfl_xor_sync(0xffffffffu, sum1, 1);
        sum1 += __shfl_xor_sync(0xffffffffu, sum1, 2);
        l0 = l0 * sc0 + sum0;
        l1 = l1 * sc1 + sum1;
#pragma unroll
        for (int nt = 0; nt < 16; nt++) {
            o[nt][0] *= sc0; o[nt][1] *= sc0;
            o[nt][2] *= sc1; o[nt][3] *= sc1;
        }

        uint32_t vHi = base + AT_VHI + vmoff;
        uint32_t vLo = base + AT_VLO + vmoff;
#pragma unroll
        for (int kk2 = 0; kk2 < 4; kk2++) {
            float p00 = sacc[2 * kk2][0],     p01 = sacc[2 * kk2][1];
            float p02 = sacc[2 * kk2][2],     p03 = sacc[2 * kk2][3];
            float p10 = sacc[2 * kk2 + 1][0], p11 = sacc[2 * kk2 + 1][1];
            float p12 = sacc[2 * kk2 + 1][2], p13 = sacc[2 * kk2 + 1][3];
            uint32_t aph[4], apl[4];
            aph[0] = pack_bf2(p00, p01);
            aph[1] = pack_bf2(p02, p03);
            aph[2] = pack_bf2(p10, p11);
            aph[3] = pack_bf2(p12, p13);
            __nv_bfloat162* hp = (__nv_bfloat162*)aph;
            apl[0] = pack_bf2(p00 - __bfloat162float(hp[0].x), p01 - __bfloat162float(hp[0].y));
            apl[1] = pack_bf2(p02 - __bfloat162float(hp[1].x), p03 - __bfloat162float(hp[1].y));
            apl[2] = pack_bf2(p10 - __bfloat162float(hp[2].x), p11 - __bfloat162float(hp[2].y));
            apl[3] = pack_bf2(p12 - __bfloat162float(hp[3].x), p13 - __bfloat162float(hp[3].y));
#pragma unroll
            for (int ng = 0; ng < 8; ng++) {
                uint32_t rv[4];
                ldsm4(rv, vHi + ng * 16 * AT_VROW + kk2 * 32);
                uint32_t b0[2] = { rv[0], rv[2] }, b1[2] = { rv[1], rv[3] };
                mma_bf16(o[2 * ng],     aph, b0);
                mma_bf16(o[2 * ng + 1], aph, b1);
                mma_bf16(o[2 * ng],     apl, b0);
                mma_bf16(o[2 * ng + 1], apl, b1);
                ldsm4(rv, vLo + ng * 16 * AT_VROW + kk2 * 32);
                uint32_t c0[2] = { rv[0], rv[2] }, c1[2] = { rv[1], rv[3] };
                mma_bf16(o[2 * ng],     aph, c0);
                mma_bf16(o[2 * ng + 1], aph, c1);
            }
        }
    }

    float inv0 = 1.f / l0, inv1 = 1.f / l1;
    int row0 = q0 + wr + g;
    size_t ob0 = (size_t)row0 * D_MODEL + h * 128 + 2 * t4;
    size_t ob1 = (size_t)(row0 + 8) * D_MODEL + h * 128 + 2 * t4;
#pragma unroll
    for (int nt = 0; nt < 16; nt++) {
        float v0 = o[nt][0] * inv0, v1 = o[nt][1] * inv0;
        float v2 = o[nt][2] * inv1, v3 = o[nt][3] * inv1;
        __nv_bfloat162 h01 = __floats2bfloat162_rn(v0, v1);
        __nv_bfloat162 h23 = __floats2bfloat162_rn(v2, v3);
        ushort2 hh0 = make_ushort2(__bfloat16_as_ushort(h01.x), __bfloat16_as_ushort(h01.y));
        ushort2 hh1 = make_ushort2(__bfloat16_as_ushort(h23.x), __bfloat16_as_ushort(h23.y));
        ushort2 ll0 = make_ushort2(
            __bfloat16_as_ushort(__float2bfloat16(v0 - __bfloat162float(h01.x))),
            __bfloat16_as_ushort(__float2bfloat16(v1 - __bfloat162float(h01.y))));
        ushort2 ll1 = make_ushort2(
            __bfloat16_as_ushort(__float2bfloat16(v2 - __bfloat162float(h23.x))),
            __bfloat16_as_ushort(__float2bfloat16(v3 - __bfloat162float(h23.y))));
        *(ushort2*)(atthi + ob0 + nt * 8) = hh0;
        *(ushort2*)(attlo + ob0 + nt * 8) = ll0;
        *(ushort2*)(atthi + ob1 + nt * 8) = hh1;
        *(ushort2*)(attlo + ob1 + nt * 8) = ll1;
    }
}

// ---------------------------------------------------------------------------
// Launch
// ---------------------------------------------------------------------------
extern "C" void kernel_launch(void* const* d_in, const int* in_sizes, int n_in,
                              void* d_out, int out_size)
{
    const float* x    = (const float*)d_in[0];
    const float* wq   = (const float*)d_in[1];
    const float* wk   = (const float*)d_in[2];
    const float* wv   = (const float*)d_in[3];
    const float* wo   = (const float*)d_in[4];
    const float* cosp = (const float*)d_in[5];
    const float* sinp = (const float*)d_in[6];

    unsigned short *xhi, *xlo, *wqkvThi, *wqkvTlo, *woThi, *woTlo;
    unsigned short *qhi, *qlo, *khi, *klo, *vthi, *vtlo, *atthi, *attlo;
    float *qkv;
    cudaGetSymbolAddress((void**)&xhi, g_xhi);
    cudaGetSymbolAddress((void**)&xlo, g_xlo);
    cudaGetSymbolAddress((void**)&wqkvThi, g_wqkvT_hi);
    cudaGetSymbolAddress((void**)&wqkvTlo, g_wqkvT_lo);
    cudaGetSymbolAddress((void**)&woThi, g_woT_hi);
    cudaGetSymbolAddress((void**)&woTlo, g_woT_lo);
    cudaGetSymbolAddress((void**)&qhi, g_qhi);
    cudaGetSymbolAddress((void**)&qlo, g_qlo);
    cudaGetSymbolAddress((void**)&khi, g_khi);
    cudaGetSymbolAddress((void**)&klo, g_klo);
    cudaGetSymbolAddress((void**)&vthi, g_vthi);
    cudaGetSymbolAddress((void**)&vtlo, g_vtlo);
    cudaGetSymbolAddress((void**)&atthi, g_atthi);
    cudaGetSymbolAddress((void**)&attlo, g_attlo);
    cudaGetSymbolAddress((void**)&qkv, g_qkv);

    cudaFuncSetAttribute(gemm_mma_kernel, cudaFuncAttributeMaxDynamicSharedMemorySize, GT_SMEM);
    cudaFuncSetAttribute(attn_mma_kernel, cudaFuncAttributeMaxDynamicSharedMemorySize, AT_SMEM);

    // 1) Split x into bf16 hi/lo
    {
        int n4 = S_LEN * D_MODEL / 4;
        split_kernel<<<(n4 + 255) / 256, 256>>>(x, xhi, xlo, n4);
    }

    // 2) Transpose+split weights (wq|wk|wv concatenated, and wo)
    {
        dim3 tb(32, 8);
        split_transpose_kernel<<<dim3(D_MODEL / 32, D_MODEL / 32), tb>>>(
            wq, wqkvThi, wqkvTlo, D_MODEL, D_MODEL);
        split_transpose_kernel<<<dim3(1024 / 32, D_MODEL / 32), tb>>>(
            wk, wqkvThi + (size_t)4096 * D_MODEL, wqkvTlo + (size_t)4096 * D_MODEL,
            D_MODEL, 1024);
        split_transpose_kernel<<<dim3(1024 / 32, D_MODEL / 32), tb>>>(
            wv, wqkvThi + (size_t)5120 * D_MODEL, wqkvTlo + (size_t)5120 * D_MODEL,
            D_MODEL, 1024);
        split_transpose_kernel<<<dim3(D_MODEL / 32, D_MODEL / 32), tb>>>(
            wo, woThi, woTlo, D_MODEL, D_MODEL);
    }

    // 3) Fused QKV projection: [2048 x 6144]
    gemm_mma_kernel<<<dim3(S_LEN / GT_BM, QKV_N / GT_BN), 256, GT_SMEM>>>(
        xhi, xlo, wqkvThi, wqkvTlo, qkv, S_LEN, QKV_N, D_MODEL);

    // 4) RoPE + scale + split Q,K; transpose + split V
    {
        int tot = S_LEN * 2560;
        rope_split_kernel<<<(tot + 255) / 256, 256>>>(qkv, cosp, sinp,
                                                      qhi, qlo, khi, klo);
        dim3 tb(32, 8);
        vsplit_transpose_kernel<<<dim3(1024 / 32, S_LEN / 32), tb>>>(qkv, vthi, vtlo);
    }

    // 5) Tensor-core flash attention -> att bf16 hi/lo
    attn_mma_kernel<<<dim3(S_LEN / 128, N_HEADS), 256, AT_SMEM>>>(
        qhi, qlo, khi, klo, vthi, vtlo, atthi, attlo);

    // 6) Output projection -> d_out
    gemm_mma_kernel<<<dim3(S_LEN / GT_BM, D_MODEL / GT_BN), 256, GT_SMEM>>>(
        atthi, attlo, woThi, woTlo, (float*)d_out, S_LEN, D_MODEL, D_MODEL);
}